// round 4
// baseline (speedup 1.0000x reference)
#include <cuda_runtime.h>
#include <math.h>

#define CN 64
#define IN_N 64
#define RN 36
#define LN 40
#define DN 1024
#define SN 256
#define DC 128
#define NCH (DN/DC)
#define SP 132
#define NT 512

// shared memory layout (floats) -- all offsets multiples of 4 (16B aligned)
#define OFF_W    0
#define OFF_IMG  (OFF_W + DC*SN)              // 32768
#define OFF_CAP  (OFF_IMG + RN*SP)            // +4752
#define OFF_SIM  (OFF_CAP + LN*SP)            // +5280
#define OFF_ATTN (OFF_SIM + LN*SP)            // +5280
#define OFF_AT   (OFF_ATTN + RN*41)           // +1476
#define OFF_INVN (OFF_AT + LN*40)             // +1600
#define OFF_RED  (OFF_INVN + LN)              // +40
#define OFF_B    (OFF_RED + LN*2)             // +80
#define SMEM_FLOATS (OFF_B + SN)

__device__ __forceinline__ float warp_sum(float v) {
    #pragma unroll
    for (int o = 16; o > 0; o >>= 1) v += __shfl_xor_sync(0xffffffffu, v, o);
    return v;
}

__global__ __launch_bounds__(NT, 1)
void graphembt_kernel(const float* __restrict__ img_g,
                      const float* __restrict__ cap_g,
                      const int*   __restrict__ lens_g,
                      const float* __restrict__ W_g,
                      const float* __restrict__ b_g,
                      float*       __restrict__ out_g)
{
    extern __shared__ float sm[];
    float* sW   = sm + OFF_W;
    float* sImg = sm + OFF_IMG;
    float* sCap = sm + OFF_CAP;
    float* sSim = sm + OFF_SIM;
    float* sAttn= sm + OFF_ATTN;
    float* sAT  = sm + OFF_AT;
    float* sInv = sm + OFF_INVN;
    float* sRed = sm + OFF_RED;
    float* sB   = sm + OFF_B;

    const int i    = blockIdx.x;
    const int c    = blockIdx.y;
    const int tid  = threadIdx.x;
    const int w    = tid >> 5;
    const int lane = tid & 31;
    const int g    = w & 7;    // l-group: rows 5g..5g+4
    const int h    = w >> 3;   // d/s half

    const float* imgB = img_g + (size_t)i * (RN * DN);
    const float* capB = cap_g + (size_t)c * (LN * DN);

    if (tid < SN/4)
        *(float4*)(sB + tid*4) = *(const float4*)(b_g + tid*4);

    // ======== Phase 1: attn[r][l] = img[i,r,:] . cap[c,l,:] ========
    // 180 threads, each a 2r x 4l tile, float4 over d
    const int rg = tid / 10;          // 0..17 (tid<180)
    const int lg = tid - rg * 10;     // 0..9
    const int r0 = 2 * rg, l0 = 4 * lg;
    float p1[2][4];
    #pragma unroll
    for (int a = 0; a < 2; a++)
        #pragma unroll
        for (int b = 0; b < 4; b++) p1[a][b] = 0.f;

    for (int k = 0; k < NCH; k++) {
        __syncthreads();
        for (int idx = tid; idx < RN*(DC/4); idx += NT) {
            int r = idx >> 5, dq = idx & 31;
            *(float4*)(sImg + r*SP + dq*4) =
                *(const float4*)(imgB + r*DN + k*DC + dq*4);
        }
        for (int idx = tid; idx < LN*(DC/4); idx += NT) {
            int l = idx >> 5, dq = idx & 31;
            *(float4*)(sCap + l*SP + dq*4) =
                *(const float4*)(capB + l*DN + k*DC + dq*4);
        }
        __syncthreads();
        if (tid < 180) {
            #pragma unroll 2
            for (int d4 = 0; d4 < DC/4; d4++) {
                float4 av[2], cv[4];
                #pragma unroll
                for (int a = 0; a < 2; a++)
                    av[a] = *(float4*)(sImg + (r0+a)*SP + d4*4);
                #pragma unroll
                for (int b = 0; b < 4; b++)
                    cv[b] = *(float4*)(sCap + (l0+b)*SP + d4*4);
                #pragma unroll
                for (int a = 0; a < 2; a++)
                    #pragma unroll
                    for (int b = 0; b < 4; b++) {
                        p1[a][b] = fmaf(av[a].x, cv[b].x, p1[a][b]);
                        p1[a][b] = fmaf(av[a].y, cv[b].y, p1[a][b]);
                        p1[a][b] = fmaf(av[a].z, cv[b].z, p1[a][b]);
                        p1[a][b] = fmaf(av[a].w, cv[b].w, p1[a][b]);
                    }
            }
        }
    }
    __syncthreads();
    if (tid < 180) {
        #pragma unroll
        for (int a = 0; a < 2; a++)
            #pragma unroll
            for (int b = 0; b < 4; b++)
                sAttn[(r0+a)*41 + (l0+b)] = p1[a][b];
    }
    __syncthreads();

    // ======== Phase 2a: leaky relu + l2norm over l (per r) ========
    if (tid < RN) {
        float ss = 0.f;
        #pragma unroll 4
        for (int l = 0; l < LN; l++) {
            float x = sAttn[tid*41 + l];
            x = (x > 0.f) ? x : 0.1f * x;
            sAttn[tid*41 + l] = x;
            ss = fmaf(x, x, ss);
        }
        float inv = 1.f / (sqrtf(ss) + 1e-8f);
        #pragma unroll 4
        for (int l = 0; l < LN; l++) sAttn[tid*41 + l] *= inv;
    }
    __syncthreads();

    // ======== Phase 2b: softmax over r (per l) -> sAT[l][r] ========
    if (tid < LN) {
        float mx = -1e30f;
        #pragma unroll 4
        for (int r = 0; r < RN; r++)
            mx = fmaxf(mx, sAttn[r*41 + tid] * 9.0f);
        float sum = 0.f;
        #pragma unroll 4
        for (int r = 0; r < RN; r++) {
            float e = expf(sAttn[r*41 + tid] * 9.0f - mx);
            sAT[tid*40 + r] = e;
            sum += e;
        }
        float inv = 1.f / sum;
        #pragma unroll 4
        for (int r = 0; r < RN; r++) sAT[tid*40 + r] *= inv;
    }

    // ======== Phase 3a: wc sum-of-squares (pass 1 over D) ========
    // warp (g,h): l rows 5g..5g+4 ; lane owns d = h*64 + lane*2 (float2)
    const int dlo = h*64 + lane*2;
    float ssq[5] = {0.f,0.f,0.f,0.f,0.f};
    for (int k = 0; k < NCH; k++) {
        __syncthreads();
        for (int idx = tid; idx < RN*(DC/4); idx += NT) {
            int r = idx >> 5, dq = idx & 31;
            *(float4*)(sImg + r*SP + dq*4) =
                *(const float4*)(imgB + r*DN + k*DC + dq*4);
        }
        __syncthreads();
        float wcx[5], wcy[5];
        #pragma unroll
        for (int ii = 0; ii < 5; ii++) { wcx[ii]=0.f; wcy[ii]=0.f; }
        #pragma unroll 3
        for (int r = 0; r < RN; r += 4) {
            float2 im[4];
            #pragma unroll
            for (int q = 0; q < 4; q++)
                im[q] = *(float2*)(sImg + (r+q)*SP + dlo);
            #pragma unroll
            for (int ii = 0; ii < 5; ii++) {
                float4 a4 = *(float4*)(sAT + (5*g+ii)*40 + r);
                wcx[ii] = fmaf(a4.x, im[0].x, wcx[ii]);
                wcy[ii] = fmaf(a4.x, im[0].y, wcy[ii]);
                wcx[ii] = fmaf(a4.y, im[1].x, wcx[ii]);
                wcy[ii] = fmaf(a4.y, im[1].y, wcy[ii]);
                wcx[ii] = fmaf(a4.z, im[2].x, wcx[ii]);
                wcy[ii] = fmaf(a4.z, im[2].y, wcy[ii]);
                wcx[ii] = fmaf(a4.w, im[3].x, wcx[ii]);
                wcy[ii] = fmaf(a4.w, im[3].y, wcy[ii]);
            }
        }
        #pragma unroll
        for (int ii = 0; ii < 5; ii++)
            ssq[ii] += wcx[ii]*wcx[ii] + wcy[ii]*wcy[ii];
    }
    #pragma unroll
    for (int ii = 0; ii < 5; ii++) {
        float s = warp_sum(ssq[ii]);
        if (lane == 0) sRed[(5*g+ii)*2 + h] = s;
    }
    __syncthreads();
    if (tid < LN)
        sInv[tid] = 1.f / (sqrtf(sRed[tid*2] + sRed[tid*2+1]) + 1e-8f);

    // ======== Phase 3b: wc -> sim -> GEMM sim @ W ========
    // GEMM: warp (g,h): l = 5g+kk ; s = 128h + lane*4 .. +3
    const int s0 = h*128 + lane*4;
    float acc[5][4];
    #pragma unroll
    for (int kk = 0; kk < 5; kk++)
        #pragma unroll
        for (int j = 0; j < 4; j++) acc[kk][j] = 0.f;

    for (int k = 0; k < NCH; k++) {
        __syncthreads();
        for (int idx = tid; idx < RN*(DC/4); idx += NT) {
            int r = idx >> 5, dq = idx & 31;
            *(float4*)(sImg + r*SP + dq*4) =
                *(const float4*)(imgB + r*DN + k*DC + dq*4);
        }
        for (int idx = tid; idx < LN*(DC/4); idx += NT) {
            int l = idx >> 5, dq = idx & 31;
            *(float4*)(sCap + l*SP + dq*4) =
                *(const float4*)(capB + l*DN + k*DC + dq*4);
        }
        for (int idx = tid; idx < DC*(SN/4); idx += NT) {
            int d = idx >> 6, sq = idx & 63;
            *(float4*)(sW + d*SN + sq*4) =
                *(const float4*)(W_g + (size_t)(k*DC + d)*SN + sq*4);
        }
        __syncthreads();

        // wc recompute for this chunk
        float wcx[5], wcy[5];
        #pragma unroll
        for (int ii = 0; ii < 5; ii++) { wcx[ii]=0.f; wcy[ii]=0.f; }
        #pragma unroll 3
        for (int r = 0; r < RN; r += 4) {
            float2 im[4];
            #pragma unroll
            for (int q = 0; q < 4; q++)
                im[q] = *(float2*)(sImg + (r+q)*SP + dlo);
            #pragma unroll
            for (int ii = 0; ii < 5; ii++) {
                float4 a4 = *(float4*)(sAT + (5*g+ii)*40 + r);
                wcx[ii] = fmaf(a4.x, im[0].x, wcx[ii]);
                wcy[ii] = fmaf(a4.x, im[0].y, wcy[ii]);
                wcx[ii] = fmaf(a4.y, im[1].x, wcx[ii]);
                wcy[ii] = fmaf(a4.y, im[1].y, wcy[ii]);
                wcx[ii] = fmaf(a4.z, im[2].x, wcx[ii]);
                wcy[ii] = fmaf(a4.z, im[2].y, wcy[ii]);
                wcx[ii] = fmaf(a4.w, im[3].x, wcx[ii]);
                wcy[ii] = fmaf(a4.w, im[3].y, wcy[ii]);
            }
        }
        #pragma unroll
        for (int ii = 0; ii < 5; ii++) {
            float inv = sInv[5*g+ii];
            float2 cp = *(float2*)(sCap + (5*g+ii)*SP + dlo);
            float v0 = fmaf(wcx[ii], inv, -cp.x);
            float v1 = fmaf(wcy[ii], inv, -cp.y);
            float2 sv; sv.x = v0*v0; sv.y = v1*v1;
            *(float2*)(sSim + (5*g+ii)*SP + dlo) = sv;
        }
        __syncthreads();

        // GEMM over this chunk, 4 d at a time
        #pragma unroll 2
        for (int d = 0; d < DC; d += 4) {
            float4 sv[5];
            #pragma unroll
            for (int kk = 0; kk < 5; kk++)
                sv[kk] = *(float4*)(sSim + (5*g+kk)*SP + d);
            #pragma unroll
            for (int dd = 0; dd < 4; dd++) {
                float4 wv = *(float4*)(sW + (d+dd)*SN + s0);
                #pragma unroll
                for (int kk = 0; kk < 5; kk++) {
                    float s = (dd==0) ? sv[kk].x : (dd==1) ? sv[kk].y
                            : (dd==2) ? sv[kk].z : sv[kk].w;
                    acc[kk][0] = fmaf(s, wv.x, acc[kk][0]);
                    acc[kk][1] = fmaf(s, wv.y, acc[kk][1]);
                    acc[kk][2] = fmaf(s, wv.z, acc[kk][2]);
                    acc[kk][3] = fmaf(s, wv.w, acc[kk][3]);
                }
            }
        }
    }

    // ======== Epilogue: +b, relu, l2norm over s (split halves), mask ========
    const int clen = lens_g[c];
    float vs[5][4];
    #pragma unroll
    for (int kk = 0; kk < 5; kk++) {
        float pss = 0.f;
        #pragma unroll
        for (int j = 0; j < 4; j++) {
            float v = acc[kk][j] + sB[s0 + j];
            v = fmaxf(v, 0.f);
            vs[kk][j] = v;
            pss = fmaf(v, v, pss);
        }
        pss = warp_sum(pss);
        if (lane == 0) sRed[(5*g+kk)*2 + h] = pss;
    }
    __syncthreads();
    if (tid < LN) {
        float ss = sRed[tid*2] + sRed[tid*2+1];
        float inv = 1.f / (sqrtf(ss) + 1e-8f);
        sInv[tid] = (tid < clen) ? inv : 0.f;
    }
    __syncthreads();

    float* outB = out_g + (size_t)(c*IN_N + i) * (LN*SN);
    #pragma unroll
    for (int kk = 0; kk < 5; kk++) {
        const int l = 5*g + kk;
        float inv = sInv[l];
        float4 o;
        o.x = vs[kk][0]*inv; o.y = vs[kk][1]*inv;
        o.z = vs[kk][2]*inv; o.w = vs[kk][3]*inv;
        *(float4*)(outB + (size_t)l*SN + s0) = o;
    }
}

extern "C" void kernel_launch(void* const* d_in, const int* in_sizes, int n_in,
                              void* d_out, int out_size)
{
    const float* img  = (const float*)d_in[0];
    const float* cap  = (const float*)d_in[1];
    const int*   lens = (const int*)  d_in[2];
    const float* W    = (const float*)d_in[5];
    const float* b    = (const float*)d_in[6];
    float* out = (float*)d_out;
    (void)in_sizes; (void)n_in; (void)out_size;

    cudaFuncSetAttribute(graphembt_kernel,
                         cudaFuncAttributeMaxDynamicSharedMemorySize,
                         SMEM_FLOATS * sizeof(float));

    dim3 grid(IN_N, CN);
    graphembt_kernel<<<grid, NT, SMEM_FLOATS * sizeof(float)>>>(
        img, cap, lens, W, b, out);
}

// round 5
// speedup vs baseline: 1.0650x; 1.0650x over previous
#include <cuda_runtime.h>
#include <math.h>

typedef unsigned long long u64;

#define CN 64
#define IN_N 64
#define RN 36
#define LN 40
#define DN 1024
#define SN 256
#define DC 128
#define NCH (DN/DC)
#define SP 132      // img/cap smem row stride (floats)
#define SDS 260     // duplicated sim row stride (floats): 128 d * 2 + pad
#define ATS 76      // duplicated attn-weight row stride (floats): 36*2 + pad
#define NT 512

// shared memory layout (floats); all offsets 16B aligned
#define OFF_W    0                    // 128*256 = 32768
#define OFF_IMG  32768                // 36*132  = 4752
#define OFF_CAP  37520                // 40*132  = 5280
#define OFF_SIMD 42800                // 40*260  = 10400 (union w/ attn+gram below)
#define OFF_ATTN 42800                // 36*41   = 1476  (dead before sim written)
#define OFF_GRAM 44280                // 36*37   = 1332  (dead before sim written)
#define OFF_ATD  53200                // 40*76   = 3040
#define OFF_INV  56240                // 40
#define OFF_RED  56280                // 80
#define OFF_B    56360                // 256
#define SMEM_FLOATS 56616             // 226464 bytes < 232448 opt-in max

// packed f32x2 FMA (Blackwell double-rate fp32; PTX-only)
#define FMA2(d, a, b, c) \
    asm("fma.rn.f32x2 %0, %1, %2, %3;" : "=l"(d) : "l"(a), "l"(b), "l"(c))
#define UNPK(lo, hi, v) \
    asm("mov.b64 {%0, %1}, %2;" : "=f"(lo), "=f"(hi) : "l"(v))

__device__ float g_gram[IN_N * RN * RN];

__device__ __forceinline__ float warp_sum(float v) {
    #pragma unroll
    for (int o = 16; o > 0; o >>= 1) v += __shfl_xor_sync(0xffffffffu, v, o);
    return v;
}

// ---- Gram precompute: G[i][r][r'] = img[i,r,:] . img[i,r',:] ----
__global__ __launch_bounds__(512)
void gram_kernel(const float* __restrict__ img_g)
{
    const int i = blockIdx.x;
    const float* base = img_g + (size_t)i * (RN * DN);
    for (int idx = threadIdx.x; idx < RN * RN; idx += 512) {
        const int r  = idx / RN;
        const int r2 = idx % RN;
        const float4* A = (const float4*)(base + r  * DN);
        const float4* B = (const float4*)(base + r2 * DN);
        float s = 0.f;
        #pragma unroll 4
        for (int q = 0; q < DN / 4; q++) {
            float4 a = A[q], b = B[q];
            s += a.x * b.x + a.y * b.y + a.z * b.z + a.w * b.w;
        }
        g_gram[i * RN * RN + idx] = s;
    }
}

__global__ __launch_bounds__(NT, 1)
void graphembt_kernel(const float* __restrict__ img_g,
                      const float* __restrict__ cap_g,
                      const int*   __restrict__ lens_g,
                      const float* __restrict__ W_g,
                      const float* __restrict__ b_g,
                      float*       __restrict__ out_g)
{
    extern __shared__ float sm[];
    float* sW   = sm + OFF_W;
    float* sImg = sm + OFF_IMG;
    float* sCap = sm + OFF_CAP;
    float* sSmD = sm + OFF_SIMD;
    float* sAttn= sm + OFF_ATTN;
    float* sGrm = sm + OFF_GRAM;
    float* sATd = sm + OFF_ATD;
    float* sInv = sm + OFF_INV;
    float* sRed = sm + OFF_RED;
    float* sB   = sm + OFF_B;

    const int i    = blockIdx.x;
    const int c    = blockIdx.y;
    const int tid  = threadIdx.x;
    const int w    = tid >> 5;
    const int lane = tid & 31;
    const int g    = w & 7;    // l-group: rows 5g..5g+4
    const int h    = w >> 3;   // d/s half

    const float* imgB = img_g + (size_t)i * (RN * DN);
    const float* capB = cap_g + (size_t)c * (LN * DN);

    if (tid < SN / 4)
        *(float4*)(sB + tid * 4) = *(const float4*)(b_g + tid * 4);

    // ======== Phase 1: attn[r][l] = img[i,r,:] . cap[c,l,:] ========
    // 90 threads, 4r x 4l register tiles, packed-over-d accumulators
    const int rg = tid / 10;
    const int lg = tid - rg * 10;
    const int r0 = 4 * rg, l0 = 4 * lg;
    u64 p2[4][4];
    #pragma unroll
    for (int a = 0; a < 4; a++)
        #pragma unroll
        for (int b = 0; b < 4; b++) p2[a][b] = 0ull;

    for (int k = 0; k < NCH; k++) {
        __syncthreads();
        for (int idx = tid; idx < RN * (DC / 4); idx += NT) {
            int r = idx >> 5, dq = idx & 31;
            *(float4*)(sImg + r * SP + dq * 4) =
                *(const float4*)(imgB + r * DN + k * DC + dq * 4);
        }
        for (int idx = tid; idx < LN * (DC / 4); idx += NT) {
            int l = idx >> 5, dq = idx & 31;
            *(float4*)(sCap + l * SP + dq * 4) =
                *(const float4*)(capB + l * DN + k * DC + dq * 4);
        }
        __syncthreads();
        if (tid < 90) {
            #pragma unroll 2
            for (int d4 = 0; d4 < DC; d4 += 4) {
                ulonglong2 av[4], cv[4];
                #pragma unroll
                for (int a = 0; a < 4; a++)
                    av[a] = *(const ulonglong2*)(sImg + (r0 + a) * SP + d4);
                #pragma unroll
                for (int b = 0; b < 4; b++)
                    cv[b] = *(const ulonglong2*)(sCap + (l0 + b) * SP + d4);
                #pragma unroll
                for (int a = 0; a < 4; a++)
                    #pragma unroll
                    for (int b = 0; b < 4; b++) {
                        FMA2(p2[a][b], av[a].x, cv[b].x, p2[a][b]);
                        FMA2(p2[a][b], av[a].y, cv[b].y, p2[a][b]);
                    }
            }
        }
    }
    __syncthreads();
    if (tid < 90) {
        #pragma unroll
        for (int a = 0; a < 4; a++)
            #pragma unroll
            for (int b = 0; b < 4; b++) {
                float lo, hi;
                UNPK(lo, hi, p2[a][b]);
                sAttn[(r0 + a) * 41 + (l0 + b)] = lo + hi;
            }
    }
    __syncthreads();

    // ======== Phase 2a: leaky relu + l2norm over l (per r) ========
    // (in parallel: stage Gram matrix into smem — disjoint region)
    if (tid < RN) {
        float ss = 0.f;
        #pragma unroll 4
        for (int l = 0; l < LN; l++) {
            float x = sAttn[tid * 41 + l];
            x = (x > 0.f) ? x : 0.1f * x;
            sAttn[tid * 41 + l] = x;
            ss = fmaf(x, x, ss);
        }
        float inv = 1.f / (sqrtf(ss) + 1e-8f);
        #pragma unroll 4
        for (int l = 0; l < LN; l++) sAttn[tid * 41 + l] *= inv;
    }
    for (int idx = tid; idx < RN * RN; idx += NT) {
        int r = idx / RN, r2 = idx - r * RN;
        sGrm[r * 37 + r2] = g_gram[i * RN * RN + idx];
    }
    __syncthreads();

    // ======== Phase 2b: softmax over r (per l), store duplicated {a,a} ====
    if (tid < LN) {
        float mx = -1e30f;
        #pragma unroll 4
        for (int r = 0; r < RN; r++)
            mx = fmaxf(mx, sAttn[r * 41 + tid] * 9.0f);
        float ev[RN];
        float sum = 0.f;
        #pragma unroll 4
        for (int r = 0; r < RN; r++) {
            float e = expf(sAttn[r * 41 + tid] * 9.0f - mx);
            ev[r] = e;
            sum += e;
        }
        float inv = 1.f / sum;
        #pragma unroll 4
        for (int r = 0; r < RN; r++) {
            float a = ev[r] * inv;
            float2 d2; d2.x = a; d2.y = a;
            *(float2*)(sATd + tid * ATS + 2 * r) = d2;
        }
    }
    __syncthreads();

    // ======== ssq via Gram: ||wc_l||^2 = a^T G a ========
    // warp w handles l in {w, w+16, w+32 (w<8)}
    {
        int lcnt = (w < 8) ? 3 : 2;
        for (int q = 0; q < lcnt; q++) {
            int l = w + 16 * q;
            float t = 0.f, t2 = 0.f;
            #pragma unroll 4
            for (int rp = 0; rp < RN; rp++) {
                float a = sATd[l * ATS + 2 * rp];          // broadcast
                t = fmaf(sGrm[lane * 37 + rp], a, t);
                if (lane < 4)
                    t2 = fmaf(sGrm[(32 + lane) * 37 + rp], a, t2);
            }
            float part = sATd[l * ATS + 2 * lane] * t;
            if (lane < 4)
                part += sATd[l * ATS + 2 * (32 + lane)] * t2;
            float ss = warp_sum(part);
            if (lane == 0) sInv[l] = 1.f / (sqrtf(ss) + 1e-8f);
        }
    }

    // ======== Phase 3: wc -> sim(dup) -> GEMM sim @ W ========
    const int dlo = h * 64 + lane * 2;       // d pair owned in wc/sim
    const int s0  = h * 128 + lane * 4;      // s quad owned in GEMM
    u64 A[5][2];
    #pragma unroll
    for (int kk = 0; kk < 5; kk++) { A[kk][0] = 0ull; A[kk][1] = 0ull; }

    for (int k = 0; k < NCH; k++) {
        __syncthreads();
        for (int idx = tid; idx < RN * (DC / 4); idx += NT) {
            int r = idx >> 5, dq = idx & 31;
            *(float4*)(sImg + r * SP + dq * 4) =
                *(const float4*)(imgB + r * DN + k * DC + dq * 4);
        }
        for (int idx = tid; idx < LN * (DC / 4); idx += NT) {
            int l = idx >> 5, dq = idx & 31;
            *(float4*)(sCap + l * SP + dq * 4) =
                *(const float4*)(capB + l * DN + k * DC + dq * 4);
        }
        for (int idx = tid; idx < DC * (SN / 4); idx += NT) {
            int d = idx >> 6, sq = idx & 63;
            *(float4*)(sW + d * SN + sq * 4) =
                *(const float4*)(W_g + (size_t)(k * DC + d) * SN + sq * 4);
        }
        __syncthreads();

        // wc for this chunk: packed over d pair
        u64 wc2[5];
        #pragma unroll
        for (int ii = 0; ii < 5; ii++) wc2[ii] = 0ull;
        #pragma unroll 3
        for (int r = 0; r < RN; r += 4) {
            u64 im0 = *(const u64*)(sImg + (r + 0) * SP + dlo);
            u64 im1 = *(const u64*)(sImg + (r + 1) * SP + dlo);
            u64 im2 = *(const u64*)(sImg + (r + 2) * SP + dlo);
            u64 im3 = *(const u64*)(sImg + (r + 3) * SP + dlo);
            #pragma unroll
            for (int ii = 0; ii < 5; ii++) {
                const float* ab = sATd + (5 * g + ii) * ATS + 2 * r;
                ulonglong2 ap0 = *(const ulonglong2*)(ab);
                ulonglong2 ap1 = *(const ulonglong2*)(ab + 4);
                FMA2(wc2[ii], ap0.x, im0, wc2[ii]);
                FMA2(wc2[ii], ap0.y, im1, wc2[ii]);
                FMA2(wc2[ii], ap1.x, im2, wc2[ii]);
                FMA2(wc2[ii], ap1.y, im3, wc2[ii]);
            }
        }
        // sim = (wc*inv - cap)^2, stored duplicated {v,v}
        #pragma unroll
        for (int ii = 0; ii < 5; ii++) {
            float wx, wy;
            UNPK(wx, wy, wc2[ii]);
            float inv = sInv[5 * g + ii];
            float2 cp = *(const float2*)(sCap + (5 * g + ii) * SP + dlo);
            float v0 = fmaf(wx, inv, -cp.x);
            float v1 = fmaf(wy, inv, -cp.y);
            float4 o;
            o.x = v0 * v0; o.y = o.x;
            o.z = v1 * v1; o.w = o.z;
            *(float4*)(sSmD + (5 * g + ii) * SDS + 2 * dlo) = o;
        }
        __syncthreads();

        // GEMM over this chunk, 4 d per iter, packed f32x2
        #pragma unroll 2
        for (int d0 = 0; d0 < DC; d0 += 4) {
            ulonglong2 w0 = *(const ulonglong2*)(sW + (d0 + 0) * SN + s0);
            ulonglong2 w1 = *(const ulonglong2*)(sW + (d0 + 1) * SN + s0);
            ulonglong2 w2 = *(const ulonglong2*)(sW + (d0 + 2) * SN + s0);
            ulonglong2 w3 = *(const ulonglong2*)(sW + (d0 + 3) * SN + s0);
            #pragma unroll
            for (int kk = 0; kk < 5; kk++) {
                const float* sr = sSmD + (5 * g + kk) * SDS + 2 * d0;
                ulonglong2 p0 = *(const ulonglong2*)(sr);
                ulonglong2 p1 = *(const ulonglong2*)(sr + 4);
                FMA2(A[kk][0], p0.x, w0.x, A[kk][0]);
                FMA2(A[kk][1], p0.x, w0.y, A[kk][1]);
                FMA2(A[kk][0], p0.y, w1.x, A[kk][0]);
                FMA2(A[kk][1], p0.y, w1.y, A[kk][1]);
                FMA2(A[kk][0], p1.x, w2.x, A[kk][0]);
                FMA2(A[kk][1], p1.x, w2.y, A[kk][1]);
                FMA2(A[kk][0], p1.y, w3.x, A[kk][0]);
                FMA2(A[kk][1], p1.y, w3.y, A[kk][1]);
            }
        }
    }

    // ======== Epilogue: +b, relu, l2norm over s (split halves), mask ====
    const int clen = lens_g[c];
    float vs[5][4];
    #pragma unroll
    for (int kk = 0; kk < 5; kk++) {
        float a0, a1, a2, a3;
        UNPK(a0, a1, A[kk][0]);
        UNPK(a2, a3, A[kk][1]);
        float pss = 0.f;
        float v;
        v = fmaxf(a0 + sB[s0 + 0], 0.f); vs[kk][0] = v; pss = fmaf(v, v, pss);
        v = fmaxf(a1 + sB[s0 + 1], 0.f); vs[kk][1] = v; pss = fmaf(v, v, pss);
        v = fmaxf(a2 + sB[s0 + 2], 0.f); vs[kk][2] = v; pss = fmaf(v, v, pss);
        v = fmaxf(a3 + sB[s0 + 3], 0.f); vs[kk][3] = v; pss = fmaf(v, v, pss);
        pss = warp_sum(pss);
        if (lane == 0) sRed[(5 * g + kk) * 2 + h] = pss;
    }
    __syncthreads();
    if (tid < LN) {
        float ss = sRed[tid * 2] + sRed[tid * 2 + 1];
        float inv = 1.f / (sqrtf(ss) + 1e-8f);
        sInv[tid] = (tid < clen) ? inv : 0.f;
    }
    __syncthreads();

    float* outB = out_g + (size_t)(c * IN_N + i) * (LN * SN);
    #pragma unroll
    for (int kk = 0; kk < 5; kk++) {
        const int l = 5 * g + kk;
        float inv = sInv[l];
        float4 o;
        o.x = vs[kk][0] * inv; o.y = vs[kk][1] * inv;
        o.z = vs[kk][2] * inv; o.w = vs[kk][3] * inv;
        *(float4*)(outB + (size_t)l * SN + s0) = o;
    }
}

extern "C" void kernel_launch(void* const* d_in, const int* in_sizes, int n_in,
                              void* d_out, int out_size)
{
    const float* img  = (const float*)d_in[0];
    const float* cap  = (const float*)d_in[1];
    const int*   lens = (const int*)  d_in[2];
    const float* W    = (const float*)d_in[5];
    const float* b    = (const float*)d_in[6];
    float* out = (float*)d_out;
    (void)in_sizes; (void)n_in; (void)out_size;

    cudaFuncSetAttribute(graphembt_kernel,
                         cudaFuncAttributeMaxDynamicSharedMemorySize,
                         SMEM_FLOATS * sizeof(float));

    gram_kernel<<<IN_N, 512>>>(img);
    dim3 grid(IN_N, CN);
    graphembt_kernel<<<grid, NT, SMEM_FLOATS * sizeof(float)>>>(
        img, cap, lens, W, b, out);
}

// round 7
// speedup vs baseline: 1.7566x; 1.6493x over previous
#include <cuda_runtime.h>
#include <math.h>
#include <stdint.h>

typedef unsigned long long u64;

#define CN 64
#define IN_N 64
#define RN 36
#define LN 40
#define DN 1024
#define SN 256
#define NT 256

#define DC3 32
#define NCH3 (DN/DC3)
#define DC1 128
#define NCH1 (DN/DC1)
#define SP1 132
#define ST3 36     // stride for A-tile / WT-tile / img / cap in phase 3

// ---- smem float offsets ----
#define OFF_A     0        // A (sim) tile 48x36
#define OFF_WT    1728     // WT tile 256x36
#define OFF_IMG   10944    // 36x36
#define OFF_CAP   12240    // 40x36
#define OFF_AT    13680    // 40x40
#define OFF_INV   15280    // 48
#define OFF_RED   15328    // 48x8
#define OFF_B     15712    // 256
#define SMEM_FLOATS 15968  // 63872 bytes -> 2 CTAs/SM
// unions (dead by phase 3):
#define OFF_IMGL  0        // phase1 img staging 36x132
#define OFF_CAPL  4752     // phase1 cap staging 40x132
#define OFF_ATTN  10944    // 36x41
#define OFF_GRAM  1728     // 36x37

__device__ float g_gram[IN_N * RN * RN];
__device__ float g_WT[SN * DN];   // W^T [s][d], tf32-rounded

// ---------------- PTX helpers ----------------
__device__ __forceinline__ uint32_t to_tf32(float v) {
    uint32_t t;
    asm("cvt.rna.tf32.f32 %0, %1;" : "=r"(t) : "f"(v));
    return t;
}
#define FMA2(d, a, b, c) \
    asm("fma.rn.f32x2 %0, %1, %2, %3;" : "=l"(d) : "l"(a), "l"(b), "l"(c))
#define UNPK(lo, hi, v) \
    asm("mov.b64 {%0, %1}, %2;" : "=f"(lo), "=f"(hi) : "l"(v))
#define MMA_TF32(d, a, b) \
    asm volatile("mma.sync.aligned.m16n8k8.row.col.f32.tf32.tf32.f32 " \
        "{%0,%1,%2,%3}, {%4,%5,%6,%7}, {%8,%9}, {%0,%1,%2,%3};" \
        : "+f"((d)[0]), "+f"((d)[1]), "+f"((d)[2]), "+f"((d)[3]) \
        : "r"((a)[0]), "r"((a)[1]), "r"((a)[2]), "r"((a)[3]), \
          "r"((b)[0]), "r"((b)[1]))

__device__ __forceinline__ float warp_sum(float v) {
    #pragma unroll
    for (int o = 16; o > 0; o >>= 1) v += __shfl_xor_sync(0xffffffffu, v, o);
    return v;
}

// ---- one-time prep kernels ----
__global__ __launch_bounds__(512)
void gram_kernel(const float* __restrict__ img_g)
{
    const int i = blockIdx.x;
    const float* base = img_g + (size_t)i * (RN * DN);
    for (int idx = threadIdx.x; idx < RN * RN; idx += 512) {
        const int r  = idx / RN;
        const int r2 = idx % RN;
        const float4* A = (const float4*)(base + r  * DN);
        const float4* B = (const float4*)(base + r2 * DN);
        float s = 0.f;
        #pragma unroll 4
        for (int q = 0; q < DN / 4; q++) {
            float4 a = A[q], b = B[q];
            s += a.x * b.x + a.y * b.y + a.z * b.z + a.w * b.w;
        }
        g_gram[i * RN * RN + idx] = s;
    }
}

__global__ __launch_bounds__(256)
void wtrans_kernel(const float* __restrict__ W)
{
    int idx = blockIdx.x * 256 + threadIdx.x;   // d = idx>>8, s = idx&255
    if (idx < DN * SN) {
        int d = idx >> 8, s = idx & 255;
        g_WT[s * DN + d] = __uint_as_float(to_tf32(W[idx]));
    }
}

// ---------------- main fused kernel ----------------
__global__ __launch_bounds__(NT, 2)
void graphembt_kernel(const float* __restrict__ img_g,
                      const float* __restrict__ cap_g,
                      const int*   __restrict__ lens_g,
                      const float* __restrict__ b_g,
                      float*       __restrict__ out_g)
{
    extern __shared__ float sm[];
    const int i    = blockIdx.x;
    const int c    = blockIdx.y;
    const int tid  = threadIdx.x;
    const int w    = tid >> 5;       // 0..7
    const int lane = tid & 31;
    const int gq   = lane >> 2;      // mma groupID 0..7
    const int tg   = lane & 3;       // mma thread-in-group

    const float* imgB = img_g + (size_t)i * (RN * DN);
    const float* capB = cap_g + (size_t)c * (LN * DN);

    if (tid < SN / 4)
        *(float4*)(sm + OFF_B + tid * 4) = *(const float4*)(b_g + tid * 4);

    // ======== Phase 1: attn[r][l] (FMA2, 90 threads, 4x4 tiles) ========
    float* sImgL = sm + OFF_IMGL;
    float* sCapL = sm + OFF_CAPL;
    const int rg = tid / 10, lg = tid - rg * 10;
    const int r0 = 4 * rg, l0 = 4 * lg;
    u64 p2[4][4];
    #pragma unroll
    for (int a = 0; a < 4; a++)
        #pragma unroll
        for (int b = 0; b < 4; b++) p2[a][b] = 0ull;

    for (int k = 0; k < NCH1; k++) {
        __syncthreads();
        for (int idx = tid; idx < RN * (DC1 / 4); idx += NT) {
            int r = idx >> 5, dq = idx & 31;
            *(float4*)(sImgL + r * SP1 + dq * 4) =
                *(const float4*)(imgB + r * DN + k * DC1 + dq * 4);
        }
        for (int idx = tid; idx < LN * (DC1 / 4); idx += NT) {
            int l = idx >> 5, dq = idx & 31;
            *(float4*)(sCapL + l * SP1 + dq * 4) =
                *(const float4*)(capB + l * DN + k * DC1 + dq * 4);
        }
        __syncthreads();
        if (tid < 90) {
            #pragma unroll 2
            for (int d4 = 0; d4 < DC1; d4 += 4) {
                ulonglong2 av[4], cv[4];
                #pragma unroll
                for (int a = 0; a < 4; a++)
                    av[a] = *(const ulonglong2*)(sImgL + (r0 + a) * SP1 + d4);
                #pragma unroll
                for (int b = 0; b < 4; b++)
                    cv[b] = *(const ulonglong2*)(sCapL + (l0 + b) * SP1 + d4);
                #pragma unroll
                for (int a = 0; a < 4; a++)
                    #pragma unroll
                    for (int b = 0; b < 4; b++) {
                        FMA2(p2[a][b], av[a].x, cv[b].x, p2[a][b]);
                        FMA2(p2[a][b], av[a].y, cv[b].y, p2[a][b]);
                    }
            }
        }
    }
    __syncthreads();
    float* sAttn = sm + OFF_ATTN;
    if (tid < 90) {
        #pragma unroll
        for (int a = 0; a < 4; a++)
            #pragma unroll
            for (int b = 0; b < 4; b++) {
                float lo, hi;
                UNPK(lo, hi, p2[a][b]);
                sAttn[(r0 + a) * 41 + (l0 + b)] = lo + hi;
            }
    }
    __syncthreads();

    // ======== Phase 2a: leaky+l2norm(l); stage Gram concurrently ========
    float* sGrm = sm + OFF_GRAM;
    if (tid < RN) {
        float ss = 0.f;
        #pragma unroll 4
        for (int l = 0; l < LN; l++) {
            float x = sAttn[tid * 41 + l];
            x = (x > 0.f) ? x : 0.1f * x;
            sAttn[tid * 41 + l] = x;
            ss = fmaf(x, x, ss);
        }
        float inv = 1.f / (sqrtf(ss) + 1e-8f);
        #pragma unroll 4
        for (int l = 0; l < LN; l++) sAttn[tid * 41 + l] *= inv;
    }
    for (int idx = tid; idx < RN * RN; idx += NT) {
        int r = idx / RN, r2 = idx - r * RN;
        sGrm[r * 37 + r2] = g_gram[i * RN * RN + idx];
    }
    __syncthreads();

    // ======== Phase 2b: softmax over r -> sAT[l][r] ========
    float* sAT = sm + OFF_AT;
    if (tid < LN) {
        float mx = -1e30f;
        #pragma unroll 4
        for (int r = 0; r < RN; r++)
            mx = fmaxf(mx, sAttn[r * 41 + tid] * 9.0f);
        float ev[RN];
        float sum = 0.f;
        #pragma unroll 4
        for (int r = 0; r < RN; r++) {
            float e = expf(sAttn[r * 41 + tid] * 9.0f - mx);
            ev[r] = e;
            sum += e;
        }
        float inv = 1.f / sum;
        #pragma unroll 4
        for (int r = 0; r < RN; r++) sAT[tid * 40 + r] = ev[r] * inv;
    }
    __syncthreads();

    // ======== ssq via Gram: ||wc_l||^2 = a^T G a ========
    float* sInv = sm + OFF_INV;
    #pragma unroll
    for (int q = 0; q < 5; q++) {
        const int l = w + 8 * q;
        float t = 0.f, t2 = 0.f;
        #pragma unroll 4
        for (int rp = 0; rp < RN; rp++) {
            float a = sAT[l * 40 + rp];
            t = fmaf(sGrm[lane * 37 + rp], a, t);
            if (lane < 4)
                t2 = fmaf(sGrm[(32 + lane) * 37 + rp], a, t2);
        }
        float part = sAT[l * 40 + lane] * t;
        if (lane < 4) part += sAT[l * 40 + 32 + lane] * t2;
        float ss = warp_sum(part);
        if (lane == 0) sInv[l] = 1.f / (sqrtf(ss) + 1e-8f);
    }

    // zero A tile (rows 40..47 must stay zero)
    for (int idx = tid; idx < (48 * ST3) / 4; idx += NT) {
        float4 z = make_float4(0.f, 0.f, 0.f, 0.f);
        *(float4*)(sm + OFF_A + idx * 4) = z;
    }
    __syncthreads();

    // ======== Phase 3: per 32-d chunk: wc -> sim -> tf32 mma.sync ========
    float* sImg = sm + OFF_IMG;
    float* sCap = sm + OFF_CAP;
    uint32_t* sAu  = (uint32_t*)(sm + OFF_A);
    uint32_t* sWTu = (uint32_t*)(sm + OFF_WT);

    float acc[3][4][4];
    #pragma unroll
    for (int mt = 0; mt < 3; mt++)
        #pragma unroll
        for (int j = 0; j < 4; j++)
            #pragma unroll
            for (int q = 0; q < 4; q++) acc[mt][j][q] = 0.f;

    for (int ch = 0; ch < NCH3; ch++) {
        // stage img/cap slices and WT tile
        for (int idx = tid; idx < RN * (DC3 / 4); idx += NT) {
            int r = idx >> 3, d4 = idx & 7;
            *(float4*)(sImg + r * ST3 + d4 * 4) =
                *(const float4*)(imgB + r * DN + ch * DC3 + d4 * 4);
        }
        for (int idx = tid; idx < LN * (DC3 / 4); idx += NT) {
            int l = idx >> 3, d4 = idx & 7;
            *(float4*)(sCap + l * ST3 + d4 * 4) =
                *(const float4*)(capB + l * DN + ch * DC3 + d4 * 4);
        }
        for (int idx = tid; idx < SN * (DC3 / 4); idx += NT) {
            int s = idx >> 3, d4 = idx & 7;
            *(float4*)(sm + OFF_WT + s * ST3 + d4 * 4) =
                *(const float4*)(g_WT + (size_t)s * DN + ch * DC3 + d4 * 4);
        }
        __syncthreads();

        // wc for this chunk: warp w owns l = 5w..5w+4, lane owns d = lane
        float wcv[5] = {0.f, 0.f, 0.f, 0.f, 0.f};
        #pragma unroll 3
        for (int r = 0; r < RN; r += 4) {
            float im0 = sImg[(r + 0) * ST3 + lane];
            float im1 = sImg[(r + 1) * ST3 + lane];
            float im2 = sImg[(r + 2) * ST3 + lane];
            float im3 = sImg[(r + 3) * ST3 + lane];
            #pragma unroll
            for (int ii = 0; ii < 5; ii++) {
                float4 a4 = *(const float4*)(sAT + (5 * w + ii) * 40 + r);
                wcv[ii] = fmaf(a4.x, im0, wcv[ii]);
                wcv[ii] = fmaf(a4.y, im1, wcv[ii]);
                wcv[ii] = fmaf(a4.z, im2, wcv[ii]);
                wcv[ii] = fmaf(a4.w, im3, wcv[ii]);
            }
        }
        #pragma unroll
        for (int ii = 0; ii < 5; ii++) {
            const int l = 5 * w + ii;
            float v = fmaf(wcv[ii], sInv[l], -sCap[l * ST3 + lane]);
            sAu[l * ST3 + lane] = to_tf32(v * v);
        }
        __syncthreads();

        // GEMM chunk: warp w -> n slice [32w, 32w+32)
        #pragma unroll
        for (int ks = 0; ks < 4; ks++) {
            const int kb = ks * 8;
            uint32_t af[3][4];
            #pragma unroll
            for (int mt = 0; mt < 3; mt++) {
                af[mt][0] = sAu[(mt * 16 + gq    ) * ST3 + kb + tg    ];
                af[mt][1] = sAu[(mt * 16 + gq + 8) * ST3 + kb + tg    ];
                af[mt][2] = sAu[(mt * 16 + gq    ) * ST3 + kb + tg + 4];
                af[mt][3] = sAu[(mt * 16 + gq + 8) * ST3 + kb + tg + 4];
            }
            uint32_t bf[4][2];
            #pragma unroll
            for (int j = 0; j < 4; j++) {
                bf[j][0] = sWTu[(32 * w + 8 * j + gq) * ST3 + kb + tg    ];
                bf[j][1] = sWTu[(32 * w + 8 * j + gq) * ST3 + kb + tg + 4];
            }
            #pragma unroll
            for (int mt = 0; mt < 3; mt++)
                #pragma unroll
                for (int j = 0; j < 4; j++)
                    MMA_TF32(acc[mt][j], af[mt], bf[j]);
        }
        __syncthreads();
    }

    // ======== Epilogue: +b, relu, per-row ssq (quad shfl), norm, store ====
    float* sRed = sm + OFF_RED;
    #pragma unroll
    for (int mt = 0; mt < 3; mt++) {
        #pragma unroll
        for (int half = 0; half < 2; half++) {
            const int l = mt * 16 + gq + 8 * half;
            float ssq = 0.f;
            #pragma unroll
            for (int j = 0; j < 4; j++) {
                const int s = 32 * w + 8 * j + 2 * tg;
                float x0 = fmaxf(acc[mt][j][2 * half]     + sm[OFF_B + s],     0.f);
                float x1 = fmaxf(acc[mt][j][2 * half + 1] + sm[OFF_B + s + 1], 0.f);
                acc[mt][j][2 * half]     = x0;
                acc[mt][j][2 * half + 1] = x1;
                ssq = fmaf(x0, x0, ssq);
                ssq = fmaf(x1, x1, ssq);
            }
            ssq += __shfl_xor_sync(0xffffffffu, ssq, 1);
            ssq += __shfl_xor_sync(0xffffffffu, ssq, 2);
            if (tg == 0) sRed[l * 8 + w] = ssq;
        }
    }
    __syncthreads();
    const int clen = lens_g[c];
    if (tid < LN) {
        float ss = 0.f;
        #pragma unroll
        for (int q = 0; q < 8; q++) ss += sRed[tid * 8 + q];
        float inv = 1.f / (sqrtf(ss) + 1e-8f);
        sInv[tid] = (tid < clen) ? inv : 0.f;
    }
    __syncthreads();

    float* outB = out_g + (size_t)(c * IN_N + i) * (LN * SN);
    #pragma unroll
    for (int mt = 0; mt < 3; mt++) {
        #pragma unroll
        for (int half = 0; half < 2; half++) {
            const int l = mt * 16 + gq + 8 * half;
            if (l < LN) {
                float inv = sInv[l];
                #pragma unroll
                for (int j = 0; j < 4; j++) {
                    const int s = 32 * w + 8 * j + 2 * tg;
                    float2 o;
                    o.x = acc[mt][j][2 * half]     * inv;
                    o.y = acc[mt][j][2 * half + 1] * inv;
                    *(float2*)(outB + (size_t)l * SN + s) = o;
                }
            }
        }
    }
}

extern "C" void kernel_launch(void* const* d_in, const int* in_sizes, int n_in,
                              void* d_out, int out_size)
{
    const float* img  = (const float*)d_in[0];
    const float* cap  = (const float*)d_in[1];
    const int*   lens = (const int*)  d_in[2];
    const float* W    = (const float*)d_in[5];
    const float* b    = (const float*)d_in[6];
    float* out = (float*)d_out;
    (void)in_sizes; (void)n_in; (void)out_size;

    cudaFuncSetAttribute(graphembt_kernel,
                         cudaFuncAttributeMaxDynamicSharedMemorySize,
                         SMEM_FLOATS * sizeof(float));

    gram_kernel<<<IN_N, 512>>>(img);
    wtrans_kernel<<<(DN * SN + 255) / 256, 256>>>(W);
    dim3 grid(IN_N, CN);
    graphembt_kernel<<<grid, NT, SMEM_FLOATS * sizeof(float)>>>(
        img, cap, lens, b, out);
}

// round 8
// speedup vs baseline: 2.0550x; 1.1699x over previous
#include <cuda_runtime.h>
#include <math.h>
#include <stdint.h>

typedef unsigned long long u64;

#define CN 64
#define IN_N 64
#define RN 36
#define LN 40
#define DN 1024
#define SN 256
#define NT 256

#define DC3 32
#define NCH3 (DN/DC3)
#define DC1 128
#define NCH1 (DN/DC1)
#define SP1 132
#define ST3 36

// ---- smem float offsets (double-buffered phase 3) ----
#define OFF_WT0   0            // 256x36
#define OFF_WT1   9216
#define OFF_IMG0  18432        // 36x36
#define OFF_IMG1  19728
#define OFF_CAP0  21024        // 40x36
#define OFF_CAP1  22464
#define OFF_A     23904        // 48x36 sim tile (single)
#define OFF_AT    25632        // 40x40
#define OFF_INV   27232        // 48
#define OFF_RED   27280        // 48x8
#define OFF_B     27664        // 256
#define SMEM_FLOATS 27920      // 111680 B -> 2 CTAs/SM
// unions (dead by phase 3):
#define OFF_IMGL  0            // phase1 img staging 36x132
#define OFF_CAPL  4752         // phase1 cap staging 40x132
#define OFF_ATTN  18432        // 36x41 (in IMG0/IMG1 region)
#define OFF_GRAM  21024        // 36x37 (in CAP0/CAP1 region)

__device__ float g_gram[IN_N * RN * RN];
__device__ float g_WT[SN * DN];   // W^T [s][d], tf32-rounded

// ---------------- PTX helpers ----------------
__device__ __forceinline__ uint32_t to_tf32(float v) {
    uint32_t t;
    asm("cvt.rna.tf32.f32 %0, %1;" : "=r"(t) : "f"(v));
    return t;
}
#define FMA2(d, a, b, c) \
    asm("fma.rn.f32x2 %0, %1, %2, %3;" : "=l"(d) : "l"(a), "l"(b), "l"(c))
#define UNPK(lo, hi, v) \
    asm("mov.b64 {%0, %1}, %2;" : "=f"(lo), "=f"(hi) : "l"(v))
#define MMA_TF32(d, a, b) \
    asm volatile("mma.sync.aligned.m16n8k8.row.col.f32.tf32.tf32.f32 " \
        "{%0,%1,%2,%3}, {%4,%5,%6,%7}, {%8,%9}, {%0,%1,%2,%3};" \
        : "+f"((d)[0]), "+f"((d)[1]), "+f"((d)[2]), "+f"((d)[3]) \
        : "r"((a)[0]), "r"((a)[1]), "r"((a)[2]), "r"((a)[3]), \
          "r"((b)[0]), "r"((b)[1]))

__device__ __forceinline__ float warp_sum(float v) {
    #pragma unroll
    for (int o = 16; o > 0; o >>= 1) v += __shfl_xor_sync(0xffffffffu, v, o);
    return v;
}

// ---- one-time prep kernels ----
// warp-per-dot Gram: G[i][r][r2] = img[i,r,:].img[i,r2,:]
__global__ __launch_bounds__(256)
void gram_kernel(const float* __restrict__ img_g)
{
    const int i    = blockIdx.x;
    const int widx = blockIdx.y * 8 + (threadIdx.x >> 5);  // 0..1295
    const int lane = threadIdx.x & 31;
    const int r  = widx / RN;
    const int r2 = widx - r * RN;
    const float* A = img_g + ((size_t)i * RN + r ) * DN;
    const float* B = img_g + ((size_t)i * RN + r2) * DN;
    float s = 0.f;
    #pragma unroll 8
    for (int q = lane; q < DN; q += 32)
        s = fmaf(__ldg(A + q), __ldg(B + q), s);
    s = warp_sum(s);
    if (lane == 0) g_gram[i * RN * RN + widx] = s;
}

__global__ __launch_bounds__(256)
void wtrans_kernel(const float* __restrict__ W)
{
    int idx = blockIdx.x * 256 + threadIdx.x;   // d = idx>>8, s = idx&255
    if (idx < DN * SN) {
        int d = idx >> 8, s = idx & 255;
        g_WT[s * DN + d] = __uint_as_float(to_tf32(W[idx]));
    }
}

// ---------------- main fused kernel ----------------
__global__ __launch_bounds__(NT, 2)
void graphembt_kernel(const float* __restrict__ img_g,
                      const float* __restrict__ cap_g,
                      const int*   __restrict__ lens_g,
                      const float* __restrict__ b_g,
                      float*       __restrict__ out_g)
{
    extern __shared__ float sm[];
    const int i    = blockIdx.x;
    const int c    = blockIdx.y;
    const int tid  = threadIdx.x;
    const int w    = tid >> 5;       // 0..7
    const int lane = tid & 31;
    const int gq   = lane >> 2;      // mma groupID 0..7
    const int tg   = lane & 3;       // mma thread-in-group

    const float* imgB = img_g + (size_t)i * (RN * DN);
    const float* capB = cap_g + (size_t)c * (LN * DN);

    if (tid < SN / 4)
        *(float4*)(sm + OFF_B + tid * 4) = *(const float4*)(b_g + tid * 4);

    // ======== Phase 1: attn[r][l] (FMA2, 240 threads, 3x2 tiles) ========
    float* sImgL = sm + OFF_IMGL;
    float* sCapL = sm + OFF_CAPL;
    const int rg1 = tid / 20, lg1 = tid - (tid / 20) * 20;
    const int r0 = 3 * rg1, l0 = 2 * lg1;
    u64 p2[3][2];
    #pragma unroll
    for (int a = 0; a < 3; a++) { p2[a][0] = 0ull; p2[a][1] = 0ull; }

    for (int k = 0; k < NCH1; k++) {
        __syncthreads();
        for (int idx = tid; idx < RN * (DC1 / 4); idx += NT) {
            int r = idx >> 5, dq = idx & 31;
            *(float4*)(sImgL + r * SP1 + dq * 4) =
                *(const float4*)(imgB + r * DN + k * DC1 + dq * 4);
        }
        for (int idx = tid; idx < LN * (DC1 / 4); idx += NT) {
            int l = idx >> 5, dq = idx & 31;
            *(float4*)(sCapL + l * SP1 + dq * 4) =
                *(const float4*)(capB + l * DN + k * DC1 + dq * 4);
        }
        __syncthreads();
        if (tid < 240) {
            #pragma unroll 2
            for (int d4 = 0; d4 < DC1; d4 += 4) {
                ulonglong2 av[3], cv[2];
                #pragma unroll
                for (int a = 0; a < 3; a++)
                    av[a] = *(const ulonglong2*)(sImgL + (r0 + a) * SP1 + d4);
                #pragma unroll
                for (int b = 0; b < 2; b++)
                    cv[b] = *(const ulonglong2*)(sCapL + (l0 + b) * SP1 + d4);
                #pragma unroll
                for (int a = 0; a < 3; a++)
                    #pragma unroll
                    for (int b = 0; b < 2; b++) {
                        FMA2(p2[a][b], av[a].x, cv[b].x, p2[a][b]);
                        FMA2(p2[a][b], av[a].y, cv[b].y, p2[a][b]);
                    }
            }
        }
    }
    __syncthreads();
    float* sAttn = sm + OFF_ATTN;
    if (tid < 240) {
        #pragma unroll
        for (int a = 0; a < 3; a++)
            #pragma unroll
            for (int b = 0; b < 2; b++) {
                float lo, hi;
                UNPK(lo, hi, p2[a][b]);
                sAttn[(r0 + a) * 41 + (l0 + b)] = lo + hi;
            }
    }
    __syncthreads();

    // ======== Phase 2a: leaky+l2norm(l); stage Gram concurrently ========
    float* sGrm = sm + OFF_GRAM;
    if (tid < RN) {
        float ss = 0.f;
        #pragma unroll 4
        for (int l = 0; l < LN; l++) {
            float x = sAttn[tid * 41 + l];
            x = (x > 0.f) ? x : 0.1f * x;
            sAttn[tid * 41 + l] = x;
            ss = fmaf(x, x, ss);
        }
        float inv = 1.f / (sqrtf(ss) + 1e-8f);
        #pragma unroll 4
        for (int l = 0; l < LN; l++) sAttn[tid * 41 + l] *= inv;
    }
    for (int idx = tid; idx < RN * RN; idx += NT) {
        int r = idx / RN, r2 = idx - (idx / RN) * RN;
        sGrm[r * 37 + r2] = g_gram[i * RN * RN + idx];
    }
    __syncthreads();

    // ======== Phase 2b: softmax over r -> sAT[l][r] ========
    float* sAT = sm + OFF_AT;
    if (tid < LN) {
        float mx = -1e30f;
        #pragma unroll 4
        for (int r = 0; r < RN; r++)
            mx = fmaxf(mx, sAttn[r * 41 + tid] * 9.0f);
        float ev[RN];
        float sum = 0.f;
        #pragma unroll 4
        for (int r = 0; r < RN; r++) {
            float e = expf(sAttn[r * 41 + tid] * 9.0f - mx);
            ev[r] = e;
            sum += e;
        }
        float inv = 1.f / sum;
        #pragma unroll 4
        for (int r = 0; r < RN; r++) sAT[tid * 40 + r] = ev[r] * inv;
    }
    __syncthreads();

    // ======== ssq via Gram: ||wc_l||^2 = a^T G a ========
    float* sInv = sm + OFF_INV;
    #pragma unroll
    for (int q = 0; q < 5; q++) {
        const int l = w + 8 * q;
        float t = 0.f, t2 = 0.f;
        #pragma unroll 4
        for (int rp = 0; rp < RN; rp++) {
            float a = sAT[l * 40 + rp];
            t = fmaf(sGrm[lane * 37 + rp], a, t);
            if (lane < 4)
                t2 = fmaf(sGrm[(32 + lane) * 37 + rp], a, t2);
        }
        float part = sAT[l * 40 + lane] * t;
        if (lane < 4) part += sAT[l * 40 + 32 + lane] * t2;
        float ss = warp_sum(part);
        if (lane == 0) sInv[l] = 1.f / (sqrtf(ss) + 1e-8f);
    }

    // zero A tile (rows 40..47 must stay zero)
    for (int idx = tid; idx < (48 * ST3) / 4; idx += NT) {
        float4 z = make_float4(0.f, 0.f, 0.f, 0.f);
        *(float4*)(sm + OFF_A + idx * 4) = z;
    }

    // ======== Phase 3: double-buffered chunks: wc -> sim -> mma.sync ======
    uint32_t* sAu = (uint32_t*)(sm + OFF_A);

    float acc[3][4][4];
    #pragma unroll
    for (int mt = 0; mt < 3; mt++)
        #pragma unroll
        for (int j = 0; j < 4; j++)
            #pragma unroll
            for (int q = 0; q < 4; q++) acc[mt][j][q] = 0.f;

    // prologue: stage chunk 0 into buffer 0
    {
        for (int idx = tid; idx < RN * (DC3 / 4); idx += NT) {
            int r = idx >> 3, d4 = idx & 7;
            *(float4*)(sm + OFF_IMG0 + r * ST3 + d4 * 4) =
                *(const float4*)(imgB + r * DN + d4 * 4);
        }
        for (int idx = tid; idx < LN * (DC3 / 4); idx += NT) {
            int l = idx >> 3, d4 = idx & 7;
            *(float4*)(sm + OFF_CAP0 + l * ST3 + d4 * 4) =
                *(const float4*)(capB + l * DN + d4 * 4);
        }
        for (int idx = tid; idx < SN * (DC3 / 4); idx += NT) {
            int s = idx >> 3, d4 = idx & 7;
            *(float4*)(sm + OFF_WT0 + s * ST3 + d4 * 4) =
                *(const float4*)(g_WT + (size_t)s * DN + d4 * 4);
        }
    }
    __syncthreads();

    for (int ch = 0; ch < NCH3; ch++) {
        const int cur = ch & 1;
        const int wtC  = cur ? OFF_WT1  : OFF_WT0;
        const int imgC = cur ? OFF_IMG1 : OFF_IMG0;
        const int capC = cur ? OFF_CAP1 : OFF_CAP0;

        // stage chunk ch+1 into the other buffer (overlaps with wc below)
        if (ch + 1 < NCH3) {
            const int wtN  = cur ? OFF_WT0  : OFF_WT1;
            const int imgN = cur ? OFF_IMG0 : OFF_IMG1;
            const int capN = cur ? OFF_CAP0 : OFF_CAP1;
            const int dof = (ch + 1) * DC3;
            for (int idx = tid; idx < RN * (DC3 / 4); idx += NT) {
                int r = idx >> 3, d4 = idx & 7;
                *(float4*)(sm + imgN + r * ST3 + d4 * 4) =
                    *(const float4*)(imgB + r * DN + dof + d4 * 4);
            }
            for (int idx = tid; idx < LN * (DC3 / 4); idx += NT) {
                int l = idx >> 3, d4 = idx & 7;
                *(float4*)(sm + capN + l * ST3 + d4 * 4) =
                    *(const float4*)(capB + l * DN + dof + d4 * 4);
            }
            for (int idx = tid; idx < SN * (DC3 / 4); idx += NT) {
                int s = idx >> 3, d4 = idx & 7;
                *(float4*)(sm + wtN + s * ST3 + d4 * 4) =
                    *(const float4*)(g_WT + (size_t)s * DN + dof + d4 * 4);
            }
        }

        // wc for this chunk: warp w owns l = 5w..5w+4, lane owns d = lane
        float wcv[5] = {0.f, 0.f, 0.f, 0.f, 0.f};
        #pragma unroll 3
        for (int r = 0; r < RN; r += 4) {
            float im0 = sm[imgC + (r + 0) * ST3 + lane];
            float im1 = sm[imgC + (r + 1) * ST3 + lane];
            float im2 = sm[imgC + (r + 2) * ST3 + lane];
            float im3 = sm[imgC + (r + 3) * ST3 + lane];
            #pragma unroll
            for (int ii = 0; ii < 5; ii++) {
                float4 a4 = *(const float4*)(sAT + (5 * w + ii) * 40 + r);
                wcv[ii] = fmaf(a4.x, im0, wcv[ii]);
                wcv[ii] = fmaf(a4.y, im1, wcv[ii]);
                wcv[ii] = fmaf(a4.z, im2, wcv[ii]);
                wcv[ii] = fmaf(a4.w, im3, wcv[ii]);
            }
        }
        #pragma unroll
        for (int ii = 0; ii < 5; ii++) {
            const int l = 5 * w + ii;
            float v = fmaf(wcv[ii], sInv[l], -sm[capC + l * ST3 + lane]);
            sAu[l * ST3 + lane] = to_tf32(v * v);
        }
        __syncthreads();   // A ready; next-chunk staging complete

        // GEMM chunk: warp w -> n slice [32w, 32w+32)
        const uint32_t* sWTu = (const uint32_t*)(sm + wtC);
        #pragma unroll
        for (int ks = 0; ks < 4; ks++) {
            const int kb = ks * 8;
            uint32_t af[3][4];
            #pragma unroll
            for (int mt = 0; mt < 3; mt++) {
                af[mt][0] = sAu[(mt * 16 + gq    ) * ST3 + kb + tg    ];
                af[mt][1] = sAu[(mt * 16 + gq + 8) * ST3 + kb + tg    ];
                af[mt][2] = sAu[(mt * 16 + gq    ) * ST3 + kb + tg + 4];
                af[mt][3] = sAu[(mt * 16 + gq + 8) * ST3 + kb + tg + 4];
            }
            uint32_t bf[4][2];
            #pragma unroll
            for (int j = 0; j < 4; j++) {
                bf[j][0] = sWTu[(32 * w + 8 * j + gq) * ST3 + kb + tg    ];
                bf[j][1] = sWTu[(32 * w + 8 * j + gq) * ST3 + kb + tg + 4];
            }
            #pragma unroll
            for (int mt = 0; mt < 3; mt++)
                #pragma unroll
                for (int j = 0; j < 4; j++)
                    MMA_TF32(acc[mt][j], af[mt], bf[j]);
        }
        __syncthreads();   // GEMM done: safe to overwrite cur buffers next iter
    }

    // ======== Epilogue: +b, relu, per-row ssq (quad shfl), norm, store ====
    float* sRed = sm + OFF_RED;
    #pragma unroll
    for (int mt = 0; mt < 3; mt++) {
        #pragma unroll
        for (int half = 0; half < 2; half++) {
            const int l = mt * 16 + gq + 8 * half;
            float ssq = 0.f;
            #pragma unroll
            for (int j = 0; j < 4; j++) {
                const int s = 32 * w + 8 * j + 2 * tg;
                float x0 = fmaxf(acc[mt][j][2 * half]     + sm[OFF_B + s],     0.f);
                float x1 = fmaxf(acc[mt][j][2 * half + 1] + sm[OFF_B + s + 1], 0.f);
                acc[mt][j][2 * half]     = x0;
                acc[mt][j][2 * half + 1] = x1;
                ssq = fmaf(x0, x0, ssq);
                ssq = fmaf(x1, x1, ssq);
            }
            ssq += __shfl_xor_sync(0xffffffffu, ssq, 1);
            ssq += __shfl_xor_sync(0xffffffffu, ssq, 2);
            if (tg == 0) sRed[l * 8 + w] = ssq;
        }
    }
    __syncthreads();
    const int clen = lens_g[c];
    if (tid < LN) {
        float ss = 0.f;
        #pragma unroll
        for (int q = 0; q < 8; q++) ss += sRed[tid * 8 + q];
        float inv = 1.f / (sqrtf(ss) + 1e-8f);
        sInv[tid] = (tid < clen) ? inv : 0.f;
    }
    __syncthreads();

    float* outB = out_g + (size_t)(c * IN_N + i) * (LN * SN);
    #pragma unroll
    for (int mt = 0; mt < 3; mt++) {
        #pragma unroll
        for (int half = 0; half < 2; half++) {
            const int l = mt * 16 + gq + 8 * half;
            if (l < LN) {
                float inv = sInv[l];
                #pragma unroll
                for (int j = 0; j < 4; j++) {
                    const int s = 32 * w + 8 * j + 2 * tg;
                    float2 o;
                    o.x = acc[mt][j][2 * half]     * inv;
                    o.y = acc[mt][j][2 * half + 1] * inv;
                    *(float2*)(outB + (size_t)l * SN + s) = o;
                }
            }
        }
    }
}

extern "C" void kernel_launch(void* const* d_in, const int* in_sizes, int n_in,
                              void* d_out, int out_size)
{
    const float* img  = (const float*)d_in[0];
    const float* cap  = (const float*)d_in[1];
    const int*   lens = (const int*)  d_in[2];
    const float* W    = (const float*)d_in[5];
    const float* b    = (const float*)d_in[6];
    float* out = (float*)d_out;
    (void)in_sizes; (void)n_in; (void)out_size;

    cudaFuncSetAttribute(graphembt_kernel,
                         cudaFuncAttributeMaxDynamicSharedMemorySize,
                         SMEM_FLOATS * sizeof(float));

    dim3 ggrid(IN_N, (RN * RN) / 8);   // 64 x 162, warp-per-dot
    gram_kernel<<<ggrid, 256>>>(img);
    wtrans_kernel<<<(DN * SN + 255) / 256, 256>>>(W);
    dim3 grid(IN_N, CN);
    graphembt_kernel<<<grid, NT, SMEM_FLOATS * sizeof(float)>>>(
        img, cap, lens, b, out);
}

// round 9
// speedup vs baseline: 2.1382x; 1.0405x over previous
#include <cuda_runtime.h>
#include <cuda_fp16.h>
#include <math.h>
#include <stdint.h>

typedef unsigned long long u64;

#define CN 64
#define IN_N 64
#define RN 36
#define LN 40
#define DN 1024
#define SN 256
#define NT 256

#define DC3 32
#define NCH3 (DN/DC3)
#define DC1 128
#define NCH1 (DN/DC1)
#define SP1 132
#define ST3 36     // img/cap fp32 stride (floats)
#define WTH 40     // WT tile stride (halves)
#define ATH 40     // A (sim) tile stride (halves)

// ---- smem float offsets ----
#define OFF_WT0   0            // 256x40 halves = 5120 floats
#define OFF_WT1   5120
#define OFF_IMG0  10240        // 36x36
#define OFF_IMG1  11536
#define OFF_CAP0  12832        // 40x36
#define OFF_CAP1  14272
#define OFF_A     15712        // 48x40 halves = 960 floats
#define OFF_AT    16672        // 40x40
#define OFF_INV   18272        // 48
#define OFF_RED   18320        // 48x8
#define OFF_B     18704        // 256
#define SMEM_FLOATS 18960      // 75840 B -> 2 CTAs/SM
// unions (dead by phase 3):
#define OFF_IMGL  0            // phase1 img staging 36x132 (in WT region)
#define OFF_CAPL  4752         // phase1 cap staging 40x132
#define OFF_ATTN  10240        // 36x41 (in IMG0/IMG1 region)
#define OFF_GRAM  12832        // 36x37 (in CAP0/CAP1 region)

__device__ float  g_gram[IN_N * RN * RN];
__device__ __half g_WT[SN * DN];   // W^T [s][d], fp16

// ---------------- PTX helpers ----------------
#define FMA2(d, a, b, c) \
    asm("fma.rn.f32x2 %0, %1, %2, %3;" : "=l"(d) : "l"(a), "l"(b), "l"(c))
#define UNPK(lo, hi, v) \
    asm("mov.b64 {%0, %1}, %2;" : "=f"(lo), "=f"(hi) : "l"(v))
#define MMA_F16(d, a, b) \
    asm volatile("mma.sync.aligned.m16n8k16.row.col.f32.f16.f16.f32 " \
        "{%0,%1,%2,%3}, {%4,%5,%6,%7}, {%8,%9}, {%0,%1,%2,%3};" \
        : "+f"((d)[0]), "+f"((d)[1]), "+f"((d)[2]), "+f"((d)[3]) \
        : "r"((a)[0]), "r"((a)[1]), "r"((a)[2]), "r"((a)[3]), \
          "r"((b)[0]), "r"((b)[1]))

__device__ __forceinline__ float warp_sum(float v) {
    #pragma unroll
    for (int o = 16; o > 0; o >>= 1) v += __shfl_xor_sync(0xffffffffu, v, o);
    return v;
}

// ---- one-time prep kernels ----
__global__ __launch_bounds__(256)
void gram_kernel(const float* __restrict__ img_g)
{
    const int i    = blockIdx.x;
    const int widx = blockIdx.y * 8 + (threadIdx.x >> 5);
    const int lane = threadIdx.x & 31;
    const int r  = widx / RN;
    const int r2 = widx - r * RN;
    const float* A = img_g + ((size_t)i * RN + r ) * DN;
    const float* B = img_g + ((size_t)i * RN + r2) * DN;
    float s = 0.f;
    #pragma unroll 8
    for (int q = lane; q < DN; q += 32)
        s = fmaf(__ldg(A + q), __ldg(B + q), s);
    s = warp_sum(s);
    if (lane == 0) g_gram[i * RN * RN + widx] = s;
}

__global__ __launch_bounds__(256)
void wtrans_kernel(const float* __restrict__ W)
{
    int idx = blockIdx.x * 256 + threadIdx.x;   // d = idx>>8, s = idx&255
    if (idx < DN * SN) {
        int d = idx >> 8, s = idx & 255;
        g_WT[s * DN + d] = __float2half(W[idx]);
    }
}

// ---------------- main fused kernel ----------------
__global__ __launch_bounds__(NT, 2)
void graphembt_kernel(const float* __restrict__ img_g,
                      const float* __restrict__ cap_g,
                      const int*   __restrict__ lens_g,
                      const float* __restrict__ b_g,
                      float*       __restrict__ out_g)
{
    extern __shared__ float sm[];
    const int i    = blockIdx.x;
    const int c    = blockIdx.y;
    const int tid  = threadIdx.x;
    const int w    = tid >> 5;       // 0..7
    const int lane = tid & 31;
    const int gq   = lane >> 2;      // mma groupID 0..7
    const int tg   = lane & 3;       // thread-in-group

    const float* imgB = img_g + (size_t)i * (RN * DN);
    const float* capB = cap_g + (size_t)c * (LN * DN);

    if (tid < SN / 4)
        *(float4*)(sm + OFF_B + tid * 4) = *(const float4*)(b_g + tid * 4);

    // ======== Phase 1: attn[r][l] (FMA2, 240 threads, 3x2 tiles) ========
    float* sImgL = sm + OFF_IMGL;
    float* sCapL = sm + OFF_CAPL;
    const int rg1 = tid / 20, lg1 = tid - (tid / 20) * 20;
    const int r0 = 3 * rg1, l0 = 2 * lg1;
    u64 p2[3][2];
    #pragma unroll
    for (int a = 0; a < 3; a++) { p2[a][0] = 0ull; p2[a][1] = 0ull; }

    for (int k = 0; k < NCH1; k++) {
        __syncthreads();
        for (int idx = tid; idx < RN * (DC1 / 4); idx += NT) {
            int r = idx >> 5, dq = idx & 31;
            *(float4*)(sImgL + r * SP1 + dq * 4) =
                *(const float4*)(imgB + r * DN + k * DC1 + dq * 4);
        }
        for (int idx = tid; idx < LN * (DC1 / 4); idx += NT) {
            int l = idx >> 5, dq = idx & 31;
            *(float4*)(sCapL + l * SP1 + dq * 4) =
                *(const float4*)(capB + l * DN + k * DC1 + dq * 4);
        }
        __syncthreads();
        if (tid < 240) {
            #pragma unroll 2
            for (int d4 = 0; d4 < DC1; d4 += 4) {
                ulonglong2 av[3], cv[2];
                #pragma unroll
                for (int a = 0; a < 3; a++)
                    av[a] = *(const ulonglong2*)(sImgL + (r0 + a) * SP1 + d4);
                #pragma unroll
                for (int b = 0; b < 2; b++)
                    cv[b] = *(const ulonglong2*)(sCapL + (l0 + b) * SP1 + d4);
                #pragma unroll
                for (int a = 0; a < 3; a++)
                    #pragma unroll
                    for (int b = 0; b < 2; b++) {
                        FMA2(p2[a][b], av[a].x, cv[b].x, p2[a][b]);
                        FMA2(p2[a][b], av[a].y, cv[b].y, p2[a][b]);
                    }
            }
        }
    }
    __syncthreads();
    float* sAttn = sm + OFF_ATTN;
    if (tid < 240) {
        #pragma unroll
        for (int a = 0; a < 3; a++)
            #pragma unroll
            for (int b = 0; b < 2; b++) {
                float lo, hi;
                UNPK(lo, hi, p2[a][b]);
                sAttn[(r0 + a) * 41 + (l0 + b)] = lo + hi;
            }
    }
    __syncthreads();

    // ======== Phase 2a: leaky+l2norm(l); stage Gram concurrently ========
    float* sGrm = sm + OFF_GRAM;
    if (tid < RN) {
        float ss = 0.f;
        #pragma unroll 4
        for (int l = 0; l < LN; l++) {
            float x = sAttn[tid * 41 + l];
            x = (x > 0.f) ? x : 0.1f * x;
            sAttn[tid * 41 + l] = x;
            ss = fmaf(x, x, ss);
        }
        float inv = 1.f / (sqrtf(ss) + 1e-8f);
        #pragma unroll 4
        for (int l = 0; l < LN; l++) sAttn[tid * 41 + l] *= inv;
    }
    for (int idx = tid; idx < RN * RN; idx += NT) {
        int r = idx / RN, r2 = idx - (idx / RN) * RN;
        sGrm[r * 37 + r2] = g_gram[i * RN * RN + idx];
    }
    __syncthreads();

    // ======== Phase 2b: softmax over r -> sAT[l][r] ========
    float* sAT = sm + OFF_AT;
    if (tid < LN) {
        float mx = -1e30f;
        #pragma unroll 4
        for (int r = 0; r < RN; r++)
            mx = fmaxf(mx, sAttn[r * 41 + tid] * 9.0f);
        float ev[RN];
        float sum = 0.f;
        #pragma unroll 4
        for (int r = 0; r < RN; r++) {
            float e = expf(sAttn[r * 41 + tid] * 9.0f - mx);
            ev[r] = e;
            sum += e;
        }
        float inv = 1.f / sum;
        #pragma unroll 4
        for (int r = 0; r < RN; r++) sAT[tid * 40 + r] = ev[r] * inv;
    }
    __syncthreads();

    // ======== ssq via Gram: ||wc_l||^2 = a^T G a ========
    float* sInv = sm + OFF_INV;
    #pragma unroll
    for (int q = 0; q < 5; q++) {
        const int l = w + 8 * q;
        float t = 0.f, t2 = 0.f;
        #pragma unroll 4
        for (int rp = 0; rp < RN; rp++) {
            float a = sAT[l * 40 + rp];
            t = fmaf(sGrm[lane * 37 + rp], a, t);
            if (lane < 4)
                t2 = fmaf(sGrm[(32 + lane) * 37 + rp], a, t2);
        }
        float part = sAT[l * 40 + lane] * t;
        if (lane < 4) part += sAT[l * 40 + 32 + lane] * t2;
        float ss = warp_sum(part);
        if (lane == 0) sInv[l] = 1.f / (sqrtf(ss) + 1e-8f);
    }

    // zero A tile (48x40 halves; rows 40..47 must stay zero)
    for (int idx = tid; idx < (48 * ATH) / 8; idx += NT) {
        float4 z = make_float4(0.f, 0.f, 0.f, 0.f);
        *(float4*)(sm + OFF_A + idx * 4) = z;
    }

    // ======== Phase 3: double-buffered chunks: wc -> sim(f16) -> mma ======
    __half* sAh = (__half*)(sm + OFF_A);

    float acc[3][4][4];
    #pragma unroll
    for (int mt = 0; mt < 3; mt++)
        #pragma unroll
        for (int j = 0; j < 4; j++)
            #pragma unroll
            for (int q = 0; q < 4; q++) acc[mt][j][q] = 0.f;

    // prologue: stage chunk 0 into buffer 0
    {
        for (int idx = tid; idx < RN * (DC3 / 4); idx += NT) {
            int r = idx >> 3, d4 = idx & 7;
            *(float4*)(sm + OFF_IMG0 + r * ST3 + d4 * 4) =
                *(const float4*)(imgB + r * DN + d4 * 4);
        }
        for (int idx = tid; idx < LN * (DC3 / 4); idx += NT) {
            int l = idx >> 3, d4 = idx & 7;
            *(float4*)(sm + OFF_CAP0 + l * ST3 + d4 * 4) =
                *(const float4*)(capB + l * DN + d4 * 4);
        }
        // WT: 256 rows x 32 halves = 4 x int4 per row
        for (int idx = tid; idx < SN * 4; idx += NT) {
            int s = idx >> 2, q = idx & 3;
            *(int4*)((char*)(sm + OFF_WT0) + s * (WTH * 2) + q * 16) =
                *(const int4*)((const char*)(g_WT + (size_t)s * DN) + q * 16);
        }
    }
    __syncthreads();

    for (int ch = 0; ch < NCH3; ch++) {
        const int cur = ch & 1;
        const int wtC  = cur ? OFF_WT1  : OFF_WT0;
        const int imgC = cur ? OFF_IMG1 : OFF_IMG0;
        const int capC = cur ? OFF_CAP1 : OFF_CAP0;

        // stage chunk ch+1 into the other buffer (overlaps with wc below)
        if (ch + 1 < NCH3) {
            const int wtN  = cur ? OFF_WT0  : OFF_WT1;
            const int imgN = cur ? OFF_IMG0 : OFF_IMG1;
            const int capN = cur ? OFF_CAP0 : OFF_CAP1;
            const int dof = (ch + 1) * DC3;
            for (int idx = tid; idx < RN * (DC3 / 4); idx += NT) {
                int r = idx >> 3, d4 = idx & 7;
                *(float4*)(sm + imgN + r * ST3 + d4 * 4) =
                    *(const float4*)(imgB + r * DN + dof + d4 * 4);
            }
            for (int idx = tid; idx < LN * (DC3 / 4); idx += NT) {
                int l = idx >> 3, d4 = idx & 7;
                *(float4*)(sm + capN + l * ST3 + d4 * 4) =
                    *(const float4*)(capB + l * DN + dof + d4 * 4);
            }
            for (int idx = tid; idx < SN * 4; idx += NT) {
                int s = idx >> 2, q = idx & 3;
                *(int4*)((char*)(sm + wtN) + s * (WTH * 2) + q * 16) =
                    *(const int4*)((const char*)(g_WT + (size_t)s * DN + dof) + q * 16);
            }
        }

        // wc for this chunk: warp w owns l = 5w..5w+4, lane owns d = lane
        float wcv[5] = {0.f, 0.f, 0.f, 0.f, 0.f};
        #pragma unroll 3
        for (int r = 0; r < RN; r += 4) {
            float im0 = sm[imgC + (r + 0) * ST3 + lane];
            float im1 = sm[imgC + (r + 1) * ST3 + lane];
            float im2 = sm[imgC + (r + 2) * ST3 + lane];
            float im3 = sm[imgC + (r + 3) * ST3 + lane];
            #pragma unroll
            for (int ii = 0; ii < 5; ii++) {
                float4 a4 = *(const float4*)(sAT + (5 * w + ii) * 40 + r);
                wcv[ii] = fmaf(a4.x, im0, wcv[ii]);
                wcv[ii] = fmaf(a4.y, im1, wcv[ii]);
                wcv[ii] = fmaf(a4.z, im2, wcv[ii]);
                wcv[ii] = fmaf(a4.w, im3, wcv[ii]);
            }
        }
        #pragma unroll
        for (int ii = 0; ii < 5; ii++) {
            const int l = 5 * w + ii;
            float v = fmaf(wcv[ii], sInv[l], -sm[capC + l * ST3 + lane]);
            sAh[l * ATH + lane] = __float2half(v * v);
        }
        __syncthreads();   // A ready; next-chunk staging complete

        // GEMM chunk: warp w -> n slice [32w, 32w+32), fp16 m16n8k16
        const __half* sWTh = (const __half*)(sm + wtC);
        #pragma unroll
        for (int ks = 0; ks < 2; ks++) {
            const int kb = ks * 16;
            uint32_t af[3][4];
            #pragma unroll
            for (int mt = 0; mt < 3; mt++) {
                af[mt][0] = *(const uint32_t*)(sAh + (mt * 16 + gq    ) * ATH + kb + 2 * tg    );
                af[mt][1] = *(const uint32_t*)(sAh + (mt * 16 + gq + 8) * ATH + kb + 2 * tg    );
                af[mt][2] = *(const uint32_t*)(sAh + (mt * 16 + gq    ) * ATH + kb + 2 * tg + 8);
                af[mt][3] = *(const uint32_t*)(sAh + (mt * 16 + gq + 8) * ATH + kb + 2 * tg + 8);
            }
            uint32_t bf[4][2];
            #pragma unroll
            for (int j = 0; j < 4; j++) {
                bf[j][0] = *(const uint32_t*)(sWTh + (32 * w + 8 * j + gq) * WTH + kb + 2 * tg    );
                bf[j][1] = *(const uint32_t*)(sWTh + (32 * w + 8 * j + gq) * WTH + kb + 2 * tg + 8);
            }
            #pragma unroll
            for (int mt = 0; mt < 3; mt++)
                #pragma unroll
                for (int j = 0; j < 4; j++)
                    MMA_F16(acc[mt][j], af[mt], bf[j]);
        }
        __syncthreads();   // GEMM done: safe to overwrite cur buffers
    }

    // ======== Epilogue: +b, relu, per-row ssq (quad shfl), norm, store ====
    float* sRed = sm + OFF_RED;
    #pragma unroll
    for (int mt = 0; mt < 3; mt++) {
        #pragma unroll
        for (int half = 0; half < 2; half++) {
            const int l = mt * 16 + gq + 8 * half;
            float ssq = 0.f;
            #pragma unroll
            for (int j = 0; j < 4; j++) {
                const int s = 32 * w + 8 * j + 2 * tg;
                float x0 = fmaxf(acc[mt][j][2 * half]     + sm[OFF_B + s],     0.f);
                float x1 = fmaxf(acc[mt][j][2 * half + 1] + sm[OFF_B + s + 1], 0.f);
                acc[mt][j][2 * half]     = x0;
                acc[mt][j][2 * half + 1] = x1;
                ssq = fmaf(x0, x0, ssq);
                ssq = fmaf(x1, x1, ssq);
            }
            ssq += __shfl_xor_sync(0xffffffffu, ssq, 1);
            ssq += __shfl_xor_sync(0xffffffffu, ssq, 2);
            if (tg == 0) sRed[l * 8 + w] = ssq;
        }
    }
    __syncthreads();
    const int clen = lens_g[c];
    if (tid < LN) {
        float ss = 0.f;
        #pragma unroll
        for (int q = 0; q < 8; q++) ss += sRed[tid * 8 + q];
        float inv = 1.f / (sqrtf(ss) + 1e-8f);
        sInv[tid] = (tid < clen) ? inv : 0.f;
    }
    __syncthreads();

    float* outB = out_g + (size_t)(c * IN_N + i) * (LN * SN);
    #pragma unroll
    for (int mt = 0; mt < 3; mt++) {
        #pragma unroll
        for (int half = 0; half < 2; half++) {
            const int l = mt * 16 + gq + 8 * half;
            if (l < LN) {
                float inv = sInv[l];
                #pragma unroll
                for (int j = 0; j < 4; j++) {
                    const int s = 32 * w + 8 * j + 2 * tg;
                    float2 o;
                    o.x = acc[mt][j][2 * half]     * inv;
                    o.y = acc[mt][j][2 * half + 1] * inv;
                    *(float2*)(outB + (size_t)l * SN + s) = o;
                }
            }
        }
    }
}

extern "C" void kernel_launch(void* const* d_in, const int* in_sizes, int n_in,
                              void* d_out, int out_size)
{
    const float* img  = (const float*)d_in[0];
    const float* cap  = (const float*)d_in[1];
    const int*   lens = (const int*)  d_in[2];
    const float* W    = (const float*)d_in[5];
    const float* b    = (const float*)d_in[6];
    float* out = (float*)d_out;
    (void)in_sizes; (void)n_in; (void)out_size;

    cudaFuncSetAttribute(graphembt_kernel,
                         cudaFuncAttributeMaxDynamicSharedMemorySize,
                         SMEM_FLOATS * sizeof(float));

    dim3 ggrid(IN_N, (RN * RN) / 8);
    gram_kernel<<<ggrid, 256>>>(img);
    wtrans_kernel<<<(DN * SN + 255) / 256, 256>>>(W);
    dim3 grid(IN_N, CN);
    graphembt_kernel<<<grid, NT, SMEM_FLOATS * sizeof(float)>>>(
        img, cap, lens, b, out);
}

// round 10
// speedup vs baseline: 2.8442x; 1.3302x over previous
#include <cuda_runtime.h>
#include <cuda_fp16.h>
#include <math.h>
#include <stdint.h>

typedef unsigned long long u64;

#define CN 64
#define IN_N 64
#define RN 36
#define LN 40
#define DN 1024
#define SN 256
#define NT 256

#define DC3 32
#define NCH3 (DN/DC3)
#define DC1 64
#define NCH1 (DN/DC1)
#define SP1 68     // phase-1 staging stride (floats)
#define ST3 36     // phase-3 img/cap stride (floats)
#define WTH 40     // WT tile stride (halves)
#define ATH 40     // A (sim) tile stride (halves)

// ---- smem float offsets ----
#define OFF_WT0   0            // 256x40 halves = 5120 floats
#define OFF_WT1   5120
#define OFF_IMG0  10240        // 36x36
#define OFF_IMG1  11536
#define OFF_CAP0  12832        // 40x36
#define OFF_CAP1  14272
#define OFF_A     15712        // 48x40 halves = 960 floats
#define OFF_AT    16672        // 40x40
#define OFF_INV   18272        // 48
#define OFF_RED   18320        // 48x8
#define OFF_B     18704        // 256
#define SMEM_FLOATS 18960      // 75840 B -> 2 CTAs/SM
// unions (dead by phase 3):
#define P1_IMG0   0            // 36x68
#define P1_IMG1   2448
#define P1_CAP0   4896         // 40x68
#define P1_CAP1   7616         // ends 10336
#define OFF_ATTN  10240        // 36x41 (after phase-1 loop + sync)
#define OFF_GRAM  12832        // 36x37 (consumed before phase-3 prologue)

__device__ float  g_gram[IN_N * RN * RN];
__device__ __half g_WT[SN * DN];   // W^T [s][d], fp16

// ---------------- PTX helpers ----------------
#define FMA2(d, a, b, c) \
    asm("fma.rn.f32x2 %0, %1, %2, %3;" : "=l"(d) : "l"(a), "l"(b), "l"(c))
#define UNPK(lo, hi, v) \
    asm("mov.b64 {%0, %1}, %2;" : "=f"(lo), "=f"(hi) : "l"(v))
#define MMA_F16(d, a, b) \
    asm volatile("mma.sync.aligned.m16n8k16.row.col.f32.f16.f16.f32 " \
        "{%0,%1,%2,%3}, {%4,%5,%6,%7}, {%8,%9}, {%0,%1,%2,%3};" \
        : "+f"((d)[0]), "+f"((d)[1]), "+f"((d)[2]), "+f"((d)[3]) \
        : "r"((a)[0]), "r"((a)[1]), "r"((a)[2]), "r"((a)[3]), \
          "r"((b)[0]), "r"((b)[1]))
#define CP16(saddr, gptr) \
    asm volatile("cp.async.cg.shared.global [%0], [%1], 16;" \
                 :: "r"(saddr), "l"(gptr) : "memory")
#define CP_COMMIT() asm volatile("cp.async.commit_group;" ::: "memory")
#define CP_WAIT0()  asm volatile("cp.async.wait_group 0;" ::: "memory")

__device__ __forceinline__ uint32_t smem_u32(const void* p) {
    uint32_t a;
    asm("{ .reg .u64 t; cvta.to.shared.u64 t, %1; cvt.u32.u64 %0, t; }"
        : "=r"(a) : "l"(p));
    return a;
}
__device__ __forceinline__ float warp_sum(float v) {
    #pragma unroll
    for (int o = 16; o > 0; o >>= 1) v += __shfl_xor_sync(0xffffffffu, v, o);
    return v;
}

// ---- one-time prep kernels ----
__global__ __launch_bounds__(256)
void gram_kernel(const float* __restrict__ img_g)
{
    const int i    = blockIdx.x;
    const int widx = blockIdx.y * 8 + (threadIdx.x >> 5);
    const int lane = threadIdx.x & 31;
    const int r  = widx / RN;
    const int r2 = widx - r * RN;
    const float* A = img_g + ((size_t)i * RN + r ) * DN;
    const float* B = img_g + ((size_t)i * RN + r2) * DN;
    float s = 0.f;
    #pragma unroll 8
    for (int q = lane; q < DN; q += 32)
        s = fmaf(__ldg(A + q), __ldg(B + q), s);
    s = warp_sum(s);
    if (lane == 0) g_gram[i * RN * RN + widx] = s;
}

__global__ __launch_bounds__(256)
void wtrans_kernel(const float* __restrict__ W)
{
    int idx = blockIdx.x * 256 + threadIdx.x;
    if (idx < DN * SN) {
        int d = idx >> 8, s = idx & 255;
        g_WT[s * DN + d] = __float2half(W[idx]);
    }
}

// ---------------- main fused kernel ----------------
__global__ __launch_bounds__(NT, 2)
void graphembt_kernel(const float* __restrict__ img_g,
                      const float* __restrict__ cap_g,
                      const int*   __restrict__ lens_g,
                      const float* __restrict__ b_g,
                      float*       __restrict__ out_g)
{
    extern __shared__ float sm[];
    const int i    = blockIdx.x;
    const int c    = blockIdx.y;
    const int tid  = threadIdx.x;
    const int w    = tid >> 5;       // 0..7
    const int lane = tid & 31;
    const int gq   = lane >> 2;      // mma groupID 0..7
    const int tg   = lane & 3;       // thread-in-group

    const uint32_t sb = smem_u32(sm);   // smem base (bytes)

    const float* imgB = img_g + (size_t)i * (RN * DN);
    const float* capB = cap_g + (size_t)c * (LN * DN);

    if (tid < SN / 4)
        *(float4*)(sm + OFF_B + tid * 4) = *(const float4*)(b_g + tid * 4);

    // ======== Phase 1: attn[r][l], cp.async double-buffered 64-d chunks ====
    const int rg1 = tid / 20, lg1 = tid - (tid / 20) * 20;
    const int r0 = 3 * rg1, l0 = 2 * lg1;
    u64 p2[3][2];
    #pragma unroll
    for (int a = 0; a < 3; a++) { p2[a][0] = 0ull; p2[a][1] = 0ull; }

    // prologue: stage chunk 0 into buffer 0
    for (int idx = tid; idx < RN * (DC1 / 4); idx += NT) {     // 576
        int r = idx >> 4, d4 = idx & 15;
        CP16(sb + (P1_IMG0 + r * SP1 + d4 * 4) * 4, imgB + r * DN + d4 * 4);
    }
    for (int idx = tid; idx < LN * (DC1 / 4); idx += NT) {     // 640
        int l = idx >> 4, d4 = idx & 15;
        CP16(sb + (P1_CAP0 + l * SP1 + d4 * 4) * 4, capB + l * DN + d4 * 4);
    }
    CP_COMMIT();

    for (int k = 0; k < NCH1; k++) {
        const int cur = k & 1;
        const int imgC = cur ? P1_IMG1 : P1_IMG0;
        const int capC = cur ? P1_CAP1 : P1_CAP0;
        CP_WAIT0();
        __syncthreads();
        if (k + 1 < NCH1) {
            const int imgN = cur ? P1_IMG0 : P1_IMG1;
            const int capN = cur ? P1_CAP0 : P1_CAP1;
            const int dof = (k + 1) * DC1;
            for (int idx = tid; idx < RN * (DC1 / 4); idx += NT) {
                int r = idx >> 4, d4 = idx & 15;
                CP16(sb + (imgN + r * SP1 + d4 * 4) * 4,
                     imgB + r * DN + dof + d4 * 4);
            }
            for (int idx = tid; idx < LN * (DC1 / 4); idx += NT) {
                int l = idx >> 4, d4 = idx & 15;
                CP16(sb + (capN + l * SP1 + d4 * 4) * 4,
                     capB + l * DN + dof + d4 * 4);
            }
            CP_COMMIT();
        }
        if (tid < 240) {
            #pragma unroll 2
            for (int d4 = 0; d4 < DC1; d4 += 4) {
                ulonglong2 av[3], cv[2];
                #pragma unroll
                for (int a = 0; a < 3; a++)
                    av[a] = *(const ulonglong2*)(sm + imgC + (r0 + a) * SP1 + d4);
                #pragma unroll
                for (int b = 0; b < 2; b++)
                    cv[b] = *(const ulonglong2*)(sm + capC + (l0 + b) * SP1 + d4);
                #pragma unroll
                for (int a = 0; a < 3; a++)
                    #pragma unroll
                    for (int b = 0; b < 2; b++) {
                        FMA2(p2[a][b], av[a].x, cv[b].x, p2[a][b]);
                        FMA2(p2[a][b], av[a].y, cv[b].y, p2[a][b]);
                    }
            }
        }
    }
    __syncthreads();
    float* sAttn = sm + OFF_ATTN;
    if (tid < 240) {
        #pragma unroll
        for (int a = 0; a < 3; a++)
            #pragma unroll
            for (int b = 0; b < 2; b++) {
                float lo, hi;
                UNPK(lo, hi, p2[a][b]);
                sAttn[(r0 + a) * 41 + (l0 + b)] = lo + hi;
            }
    }
    __syncthreads();

    // ======== Phase 2a: leaky+l2norm(l); stage Gram concurrently ========
    float* sGrm = sm + OFF_GRAM;
    if (tid < RN) {
        float ss = 0.f;
        #pragma unroll 4
        for (int l = 0; l < LN; l++) {
            float x = sAttn[tid * 41 + l];
            x = (x > 0.f) ? x : 0.1f * x;
            sAttn[tid * 41 + l] = x;
            ss = fmaf(x, x, ss);
        }
        float inv = 1.f / (sqrtf(ss) + 1e-8f);
        #pragma unroll 4
        for (int l = 0; l < LN; l++) sAttn[tid * 41 + l] *= inv;
    }
    for (int idx = tid; idx < RN * RN; idx += NT) {
        int r = idx / RN, r2 = idx - (idx / RN) * RN;
        sGrm[r * 37 + r2] = g_gram[i * RN * RN + idx];
    }
    __syncthreads();

    // ======== Phase 2b: softmax over r -> sAT[l][r] ========
    float* sAT = sm + OFF_AT;
    if (tid < LN) {
        float mx = -1e30f;
        #pragma unroll 4
        for (int r = 0; r < RN; r++)
            mx = fmaxf(mx, sAttn[r * 41 + tid] * 9.0f);
        float ev[RN];
        float sum = 0.f;
        #pragma unroll 4
        for (int r = 0; r < RN; r++) {
            float e = expf(sAttn[r * 41 + tid] * 9.0f - mx);
            ev[r] = e;
            sum += e;
        }
        float inv = 1.f / sum;
        #pragma unroll 4
        for (int r = 0; r < RN; r++) sAT[tid * 40 + r] = ev[r] * inv;
    }
    __syncthreads();

    // ======== ssq via Gram: ||wc_l||^2 = a^T G a ========
    float* sInv = sm + OFF_INV;
    #pragma unroll
    for (int q = 0; q < 5; q++) {
        const int l = w + 8 * q;
        float t = 0.f, t2 = 0.f;
        #pragma unroll 4
        for (int rp = 0; rp < RN; rp++) {
            float a = sAT[l * 40 + rp];
            t = fmaf(sGrm[lane * 37 + rp], a, t);
            if (lane < 4)
                t2 = fmaf(sGrm[(32 + lane) * 37 + rp], a, t2);
        }
        float part = sAT[l * 40 + lane] * t;
        if (lane < 4) part += sAT[l * 40 + 32 + lane] * t2;
        float ss = warp_sum(part);
        if (lane == 0) sInv[l] = 1.f / (sqrtf(ss) + 1e-8f);
    }
    __syncthreads();   // sGrm fully consumed; phase-3 buffers may be written

    // zero A tile (48x40 halves; rows 40..47 must stay zero)
    for (int idx = tid; idx < (48 * ATH) / 8; idx += NT) {
        float4 z = make_float4(0.f, 0.f, 0.f, 0.f);
        *(float4*)(sm + OFF_A + idx * 4) = z;
    }

    // prologue: cp.async stage chunk 0 into buffer 0
    for (int idx = tid; idx < RN * (DC3 / 4); idx += NT) {
        int r = idx >> 3, d4 = idx & 7;
        CP16(sb + (OFF_IMG0 + r * ST3 + d4 * 4) * 4, imgB + r * DN + d4 * 4);
    }
    for (int idx = tid; idx < LN * (DC3 / 4); idx += NT) {
        int l = idx >> 3, d4 = idx & 7;
        CP16(sb + (OFF_CAP0 + l * ST3 + d4 * 4) * 4, capB + l * DN + d4 * 4);
    }
    for (int idx = tid; idx < SN * 4; idx += NT) {
        int s = idx >> 2, q = idx & 3;
        CP16(sb + OFF_WT0 * 4 + s * (WTH * 2) + q * 16,
             (const char*)(g_WT + (size_t)s * DN) + q * 16);
    }
    CP_COMMIT();

    // ======== Phase 3: cp.async double-buffered: wc -> sim(f16) -> mma ====
    __half* sAh = (__half*)(sm + OFF_A);
    float acc[3][4][4];
    #pragma unroll
    for (int mt = 0; mt < 3; mt++)
        #pragma unroll
        for (int j = 0; j < 4; j++)
            #pragma unroll
            for (int q = 0; q < 4; q++) acc[mt][j][q] = 0.f;

    for (int ch = 0; ch < NCH3; ch++) {
        const int cur = ch & 1;
        const int wtC  = cur ? OFF_WT1  : OFF_WT0;
        const int imgC = cur ? OFF_IMG1 : OFF_IMG0;
        const int capC = cur ? OFF_CAP1 : OFF_CAP0;

        CP_WAIT0();          // stage(ch) complete
        __syncthreads();     // visible to all; all warps past gemm(ch-1)

        if (ch + 1 < NCH3) {
            const int wtN  = cur ? OFF_WT0  : OFF_WT1;
            const int imgN = cur ? OFF_IMG0 : OFF_IMG1;
            const int capN = cur ? OFF_CAP0 : OFF_CAP1;
            const int dof = (ch + 1) * DC3;
            for (int idx = tid; idx < RN * (DC3 / 4); idx += NT) {
                int r = idx >> 3, d4 = idx & 7;
                CP16(sb + (imgN + r * ST3 + d4 * 4) * 4,
                     imgB + r * DN + dof + d4 * 4);
            }
            for (int idx = tid; idx < LN * (DC3 / 4); idx += NT) {
                int l = idx >> 3, d4 = idx & 7;
                CP16(sb + (capN + l * ST3 + d4 * 4) * 4,
                     capB + l * DN + dof + d4 * 4);
            }
            for (int idx = tid; idx < SN * 4; idx += NT) {
                int s = idx >> 2, q = idx & 3;
                CP16(sb + wtN * 4 + s * (WTH * 2) + q * 16,
                     (const char*)(g_WT + (size_t)s * DN + dof) + q * 16);
            }
            CP_COMMIT();
        }

        // wc: warp w owns l = 5w..5w+4, lane owns d = lane
        float wcv[5] = {0.f, 0.f, 0.f, 0.f, 0.f};
        #pragma unroll 3
        for (int r = 0; r < RN; r += 4) {
            float im0 = sm[imgC + (r + 0) * ST3 + lane];
            float im1 = sm[imgC + (r + 1) * ST3 + lane];
            float im2 = sm[imgC + (r + 2) * ST3 + lane];
            float im3 = sm[imgC + (r + 3) * ST3 + lane];
            #pragma unroll
            for (int ii = 0; ii < 5; ii++) {
                float4 a4 = *(const float4*)(sAT + (5 * w + ii) * 40 + r);
                wcv[ii] = fmaf(a4.x, im0, wcv[ii]);
                wcv[ii] = fmaf(a4.y, im1, wcv[ii]);
                wcv[ii] = fmaf(a4.z, im2, wcv[ii]);
                wcv[ii] = fmaf(a4.w, im3, wcv[ii]);
            }
        }
        #pragma unroll
        for (int ii = 0; ii < 5; ii++) {
            const int l = 5 * w + ii;
            float v = fmaf(wcv[ii], sInv[l], -sm[capC + l * ST3 + lane]);
            sAh[l * ATH + lane] = __float2half(v * v);
        }
        __syncthreads();   // sim tile ready

        // GEMM: warp w -> n slice [32w, 32w+32), fp16 m16n8k16
        const __half* sWTh = (const __half*)(sm + wtC);
        #pragma unroll
        for (int ks = 0; ks < 2; ks++) {
            const int kb = ks * 16;
            uint32_t af[3][4];
            #pragma unroll
            for (int mt = 0; mt < 3; mt++) {
                af[mt][0] = *(const uint32_t*)(sAh + (mt * 16 + gq    ) * ATH + kb + 2 * tg    );
                af[mt][1] = *(const uint32_t*)(sAh + (mt * 16 + gq + 8) * ATH + kb + 2 * tg    );
                af[mt][2] = *(const uint32_t*)(sAh + (mt * 16 + gq    ) * ATH + kb + 2 * tg + 8);
                af[mt][3] = *(const uint32_t*)(sAh + (mt * 16 + gq + 8) * ATH + kb + 2 * tg + 8);
            }
            uint32_t bf[4][2];
            #pragma unroll
            for (int j = 0; j < 4; j++) {
                bf[j][0] = *(const uint32_t*)(sWTh + (32 * w + 8 * j + gq) * WTH + kb + 2 * tg    );
                bf[j][1] = *(const uint32_t*)(sWTh + (32 * w + 8 * j + gq) * WTH + kb + 2 * tg + 8);
            }
            #pragma unroll
            for (int mt = 0; mt < 3; mt++)
                #pragma unroll
                for (int j = 0; j < 4; j++)
                    MMA_F16(acc[mt][j], af[mt], bf[j]);
        }
    }

    // ======== Epilogue: +b, relu, per-row ssq (quad shfl), norm, store ====
    __syncthreads();
    float* sRed = sm + OFF_RED;
    #pragma unroll
    for (int mt = 0; mt < 3; mt++) {
        #pragma unroll
        for (int half = 0; half < 2; half++) {
            const int l = mt * 16 + gq + 8 * half;
            float ssq = 0.f;
            #pragma unroll
            for (int j = 0; j < 4; j++) {
                const int s = 32 * w + 8 * j + 2 * tg;
                float x0 = fmaxf(acc[mt][j][2 * half]     + sm[OFF_B + s],     0.f);
                float x1 = fmaxf(acc[mt][j][2 * half + 1] + sm[OFF_B + s + 1], 0.f);
                acc[mt][j][2 * half]     = x0;
                acc[mt][j][2 * half + 1] = x1;
                ssq = fmaf(x0, x0, ssq);
                ssq = fmaf(x1, x1, ssq);
            }
            ssq += __shfl_xor_sync(0xffffffffu, ssq, 1);
            ssq += __shfl_xor_sync(0xffffffffu, ssq, 2);
            if (tg == 0) sRed[l * 8 + w] = ssq;
        }
    }
    __syncthreads();
    const int clen = lens_g[c];
    if (tid < LN) {
        float ss = 0.f;
        #pragma unroll
        for (int q = 0; q < 8; q++) ss += sRed[tid * 8 + q];
        float inv = 1.f / (sqrtf(ss) + 1e-8f);
        sInv[tid] = (tid < clen) ? inv : 0.f;
    }
    __syncthreads();

    float* outB = out_g + (size_t)(c * IN_N + i) * (LN * SN);
    #pragma unroll
    for (int mt = 0; mt < 3; mt++) {
        #pragma unroll
        for (int half = 0; half < 2; half++) {
            const int l = mt * 16 + gq + 8 * half;
            if (l < LN) {
                float inv = sInv[l];
                #pragma unroll
                for (int j = 0; j < 4; j++) {
                    const int s = 32 * w + 8 * j + 2 * tg;
                    float2 o;
                    o.x = acc[mt][j][2 * half]     * inv;
                    o.y = acc[mt][j][2 * half + 1] * inv;
                    *(float2*)(outB + (size_t)l * SN + s) = o;
                }
            }
        }
    }
}

extern "C" void kernel_launch(void* const* d_in, const int* in_sizes, int n_in,
                              void* d_out, int out_size)
{
    const float* img  = (const float*)d_in[0];
    const float* cap  = (const float*)d_in[1];
    const int*   lens = (const int*)  d_in[2];
    const float* W    = (const float*)d_in[5];
    const float* b    = (const float*)d_in[6];
    float* out = (float*)d_out;
    (void)in_sizes; (void)n_in; (void)out_size;

    cudaFuncSetAttribute(graphembt_kernel,
                         cudaFuncAttributeMaxDynamicSharedMemorySize,
                         SMEM_FLOATS * sizeof(float));

    dim3 ggrid(IN_N, (RN * RN) / 8);
    gram_kernel<<<ggrid, 256>>>(img);
    wtrans_kernel<<<(DN * SN + 255) / 256, 256>>>(W);
    dim3 grid(IN_N, CN);
    graphembt_kernel<<<grid, NT, SMEM_FLOATS * sizeof(float)>>>(
        img, cap, lens, b, out);
}

// round 11
// speedup vs baseline: 2.8483x; 1.0014x over previous
#include <cuda_runtime.h>
#include <cuda_fp16.h>
#include <math.h>
#include <stdint.h>

typedef unsigned long long u64;

#define CN 64
#define IN_N 64
#define RN 36
#define LN 40
#define DN 1024
#define SN 256
#define NT 256

#define DC3 32
#define NCH3 (DN/DC3)
#define DC1 64
#define NCH1 (DN/DC1)
#define SP1 68     // phase-1 staging stride (floats)
#define ST3 36     // phase-3 img/cap stride (floats)
#define WTH 40     // WT tile stride (halves)
#define ATH 40     // A (sim) tile stride (halves)

// ---- smem float offsets ----
#define OFF_WT0   0            // 256x40 halves = 5120 floats each
#define OFF_WT1   5120
#define OFF_WT2   10240
#define OFF_IMG0  15360        // 36x36
#define OFF_IMG1  16656
#define OFF_CAP0  17952        // 40x36
#define OFF_CAP1  19392
#define OFF_A0    20832        // 48x40 halves = 960 floats
#define OFF_A1    21792
#define OFF_AT    22752        // 40x40
#define OFF_INV   24352        // 48
#define OFF_RED   24400        // 48x8
#define OFF_B     24784        // 256
#define SMEM_FLOATS 25040      // 100160 B -> 2 CTAs/SM
// unions (dead by phase 3):
#define P1_IMG0   0            // 36x68
#define P1_IMG1   2448
#define P1_CAP0   4896         // 40x68
#define P1_CAP1   7616         // ends 10336 (inside WT region)
#define OFF_ATTN  15360        // 36x41 (IMG region)
#define OFF_GRAM  17952        // 36x37 (CAP region)

__device__ float  g_gram[IN_N * RN * RN];
__device__ __half g_WT[SN * DN];   // W^T [s][d], fp16

// ---------------- PTX helpers ----------------
#define FMA2(d, a, b, c) \
    asm("fma.rn.f32x2 %0, %1, %2, %3;" : "=l"(d) : "l"(a), "l"(b), "l"(c))
#define UNPK(lo, hi, v) \
    asm("mov.b64 {%0, %1}, %2;" : "=f"(lo), "=f"(hi) : "l"(v))
#define MMA_F16(d, a, b) \
    asm volatile("mma.sync.aligned.m16n8k16.row.col.f32.f16.f16.f32 " \
        "{%0,%1,%2,%3}, {%4,%5,%6,%7}, {%8,%9}, {%0,%1,%2,%3};" \
        : "+f"((d)[0]), "+f"((d)[1]), "+f"((d)[2]), "+f"((d)[3]) \
        : "r"((a)[0]), "r"((a)[1]), "r"((a)[2]), "r"((a)[3]), \
          "r"((b)[0]), "r"((b)[1]))
#define CP16(saddr, gptr) \
    asm volatile("cp.async.cg.shared.global [%0], [%1], 16;" \
                 :: "r"(saddr), "l"(gptr) : "memory")
#define CP_COMMIT() asm volatile("cp.async.commit_group;" ::: "memory")
#define CP_WAIT0()  asm volatile("cp.async.wait_group 0;" ::: "memory")

__device__ __forceinline__ uint32_t smem_u32(const void* p) {
    uint32_t a;
    asm("{ .reg .u64 t; cvta.to.shared.u64 t, %1; cvt.u32.u64 %0, t; }"
        : "=r"(a) : "l"(p));
    return a;
}
__device__ __forceinline__ float warp_sum(float v) {
    #pragma unroll
    for (int o = 16; o > 0; o >>= 1) v += __shfl_xor_sync(0xffffffffu, v, o);
    return v;
}

__device__ __forceinline__ void gemm_step(const __half* __restrict__ sAh,
                                          const __half* __restrict__ sWTh,
                                          float (&acc)[3][4][4],
                                          int w, int gq, int tg)
{
    #pragma unroll
    for (int ks = 0; ks < 2; ks++) {
        const int kb = ks * 16;
        uint32_t af[3][4];
        #pragma unroll
        for (int mt = 0; mt < 3; mt++) {
            af[mt][0] = *(const uint32_t*)(sAh + (mt * 16 + gq    ) * ATH + kb + 2 * tg    );
            af[mt][1] = *(const uint32_t*)(sAh + (mt * 16 + gq + 8) * ATH + kb + 2 * tg    );
            af[mt][2] = *(const uint32_t*)(sAh + (mt * 16 + gq    ) * ATH + kb + 2 * tg + 8);
            af[mt][3] = *(const uint32_t*)(sAh + (mt * 16 + gq + 8) * ATH + kb + 2 * tg + 8);
        }
        uint32_t bf[4][2];
        #pragma unroll
        for (int j = 0; j < 4; j++) {
            bf[j][0] = *(const uint32_t*)(sWTh + (32 * w + 8 * j + gq) * WTH + kb + 2 * tg    );
            bf[j][1] = *(const uint32_t*)(sWTh + (32 * w + 8 * j + gq) * WTH + kb + 2 * tg + 8);
        }
        #pragma unroll
        for (int mt = 0; mt < 3; mt++)
            #pragma unroll
            for (int j = 0; j < 4; j++)
                MMA_F16(acc[mt][j], af[mt], bf[j]);
    }
}

// ---- one-time prep kernels ----
__global__ __launch_bounds__(256)
void gram_kernel(const float* __restrict__ img_g)
{
    const int i    = blockIdx.x;
    const int widx = blockIdx.y * 8 + (threadIdx.x >> 5);
    const int lane = threadIdx.x & 31;
    const int r  = widx / RN;
    const int r2 = widx - r * RN;
    const float* A = img_g + ((size_t)i * RN + r ) * DN;
    const float* B = img_g + ((size_t)i * RN + r2) * DN;
    float s = 0.f;
    #pragma unroll 8
    for (int q = lane; q < DN; q += 32)
        s = fmaf(__ldg(A + q), __ldg(B + q), s);
    s = warp_sum(s);
    if (lane == 0) g_gram[i * RN * RN + widx] = s;
}

__global__ __launch_bounds__(256)
void wtrans_kernel(const float* __restrict__ W)
{
    int idx = blockIdx.x * 256 + threadIdx.x;
    if (idx < DN * SN) {
        int d = idx >> 8, s = idx & 255;
        g_WT[s * DN + d] = __float2half(W[idx]);
    }
}

// ---------------- main fused kernel ----------------
__global__ __launch_bounds__(NT, 2)
void graphembt_kernel(const float* __restrict__ img_g,
                      const float* __restrict__ cap_g,
                      const int*   __restrict__ lens_g,
                      const float* __restrict__ b_g,
                      float*       __restrict__ out_g)
{
    extern __shared__ float sm[];
    const int i    = blockIdx.x;
    const int c    = blockIdx.y;
    const int tid  = threadIdx.x;
    const int w    = tid >> 5;       // 0..7
    const int lane = tid & 31;
    const int gq   = lane >> 2;
    const int tg   = lane & 3;

    const uint32_t sb = smem_u32(sm);

    const float* imgB = img_g + (size_t)i * (RN * DN);
    const float* capB = cap_g + (size_t)c * (LN * DN);

    if (tid < SN / 4)
        *(float4*)(sm + OFF_B + tid * 4) = *(const float4*)(b_g + tid * 4);

    // ======== Phase 1: attn[r][l], cp.async double-buffered 64-d chunks ====
    const int rg1 = tid / 20, lg1 = tid - (tid / 20) * 20;
    const int r0 = 3 * rg1, l0 = 2 * lg1;
    u64 p2[3][2];
    #pragma unroll
    for (int a = 0; a < 3; a++) { p2[a][0] = 0ull; p2[a][1] = 0ull; }

    for (int idx = tid; idx < RN * (DC1 / 4); idx += NT) {
        int r = idx >> 4, d4 = idx & 15;
        CP16(sb + (P1_IMG0 + r * SP1 + d4 * 4) * 4, imgB + r * DN + d4 * 4);
    }
    for (int idx = tid; idx < LN * (DC1 / 4); idx += NT) {
        int l = idx >> 4, d4 = idx & 15;
        CP16(sb + (P1_CAP0 + l * SP1 + d4 * 4) * 4, capB + l * DN + d4 * 4);
    }
    CP_COMMIT();

    for (int k = 0; k < NCH1; k++) {
        const int cur = k & 1;
        const int imgC = cur ? P1_IMG1 : P1_IMG0;
        const int capC = cur ? P1_CAP1 : P1_CAP0;
        CP_WAIT0();
        __syncthreads();
        if (k + 1 < NCH1) {
            const int imgN = cur ? P1_IMG0 : P1_IMG1;
            const int capN = cur ? P1_CAP0 : P1_CAP1;
            const int dof = (k + 1) * DC1;
            for (int idx = tid; idx < RN * (DC1 / 4); idx += NT) {
                int r = idx >> 4, d4 = idx & 15;
                CP16(sb + (imgN + r * SP1 + d4 * 4) * 4,
                     imgB + r * DN + dof + d4 * 4);
            }
            for (int idx = tid; idx < LN * (DC1 / 4); idx += NT) {
                int l = idx >> 4, d4 = idx & 15;
                CP16(sb + (capN + l * SP1 + d4 * 4) * 4,
                     capB + l * DN + dof + d4 * 4);
            }
            CP_COMMIT();
        }
        if (tid < 240) {
            #pragma unroll 2
            for (int d4 = 0; d4 < DC1; d4 += 4) {
                ulonglong2 av[3], cv[2];
                #pragma unroll
                for (int a = 0; a < 3; a++)
                    av[a] = *(const ulonglong2*)(sm + imgC + (r0 + a) * SP1 + d4);
                #pragma unroll
                for (int b = 0; b < 2; b++)
                    cv[b] = *(const ulonglong2*)(sm + capC + (l0 + b) * SP1 + d4);
                #pragma unroll
                for (int a = 0; a < 3; a++)
                    #pragma unroll
                    for (int b = 0; b < 2; b++) {
                        FMA2(p2[a][b], av[a].x, cv[b].x, p2[a][b]);
                        FMA2(p2[a][b], av[a].y, cv[b].y, p2[a][b]);
                    }
            }
        }
    }
    __syncthreads();
    float* sAttn = sm + OFF_ATTN;
    if (tid < 240) {
        #pragma unroll
        for (int a = 0; a < 3; a++)
            #pragma unroll
            for (int b = 0; b < 2; b++) {
                float lo, hi;
                UNPK(lo, hi, p2[a][b]);
                sAttn[(r0 + a) * 41 + (l0 + b)] = lo + hi;
            }
    }
    __syncthreads();

    // ======== Phase 2a: leaky+l2norm(l); stage Gram concurrently ========
    float* sGrm = sm + OFF_GRAM;
    if (tid < RN) {
        float ss = 0.f;
        #pragma unroll 4
        for (int l = 0; l < LN; l++) {
            float x = sAttn[tid * 41 + l];
            x = (x > 0.f) ? x : 0.1f * x;
            sAttn[tid * 41 + l] = x;
            ss = fmaf(x, x, ss);
        }
        float inv = 1.f / (sqrtf(ss) + 1e-8f);
        #pragma unroll 4
        for (int l = 0; l < LN; l++) sAttn[tid * 41 + l] *= inv;
    }
    for (int idx = tid; idx < RN * RN; idx += NT) {
        int r = idx / RN, r2 = idx - (idx / RN) * RN;
        sGrm[r * 37 + r2] = g_gram[i * RN * RN + idx];
    }
    __syncthreads();

    // ======== Phase 2b: softmax over r -> sAT[l][r] ========
    float* sAT = sm + OFF_AT;
    if (tid < LN) {
        float mx = -1e30f;
        #pragma unroll 4
        for (int r = 0; r < RN; r++)
            mx = fmaxf(mx, sAttn[r * 41 + tid] * 9.0f);
        float ev[RN];
        float sum = 0.f;
        #pragma unroll 4
        for (int r = 0; r < RN; r++) {
            float e = expf(sAttn[r * 41 + tid] * 9.0f - mx);
            ev[r] = e;
            sum += e;
        }
        float inv = 1.f / sum;
        #pragma unroll 4
        for (int r = 0; r < RN; r++) sAT[tid * 40 + r] = ev[r] * inv;
    }
    __syncthreads();

    // ======== ssq via Gram: ||wc_l||^2 = a^T G a ========
    float* sInv = sm + OFF_INV;
    #pragma unroll
    for (int q = 0; q < 5; q++) {
        const int l = w + 8 * q;
        float t = 0.f, t2 = 0.f;
        #pragma unroll 4
        for (int rp = 0; rp < RN; rp++) {
            float a = sAT[l * 40 + rp];
            t = fmaf(sGrm[lane * 37 + rp], a, t);
            if (lane < 4)
                t2 = fmaf(sGrm[(32 + lane) * 37 + rp], a, t2);
        }
        float part = sAT[l * 40 + lane] * t;
        if (lane < 4) part += sAT[l * 40 + 32 + lane] * t2;
        float ss = warp_sum(part);
        if (lane == 0) sInv[l] = 1.f / (sqrtf(ss) + 1e-8f);
    }
    __syncthreads();   // sGrm/sAttn consumed; phase-3 buffers free

    // zero both A tiles (rows 40..47 must stay zero)
    for (int idx = tid; idx < 480; idx += NT) {
        float4 z = make_float4(0.f, 0.f, 0.f, 0.f);
        *(float4*)(sm + OFF_A0 + idx * 4) = z;   // covers A0 and A1 (contiguous)
    }

    // hoist per-warp inverse norms (l = 5w..5w+4)
    float invl[5];
    #pragma unroll
    for (int ii = 0; ii < 5; ii++) invl[ii] = sInv[5 * w + ii];

    // prologue: stage chunk 0 (WT[0], img0, cap0)
    for (int idx = tid; idx < RN * (DC3 / 4); idx += NT) {
        int r = idx >> 3, d4 = idx & 7;
        CP16(sb + (OFF_IMG0 + r * ST3 + d4 * 4) * 4, imgB + r * DN + d4 * 4);
    }
    for (int idx = tid; idx < LN * (DC3 / 4); idx += NT) {
        int l = idx >> 3, d4 = idx & 7;
        CP16(sb + (OFF_CAP0 + l * ST3 + d4 * 4) * 4, capB + l * DN + d4 * 4);
    }
    for (int idx = tid; idx < SN * 4; idx += NT) {
        int s = idx >> 2, q = idx & 3;
        CP16(sb + OFF_WT0 * 4 + s * (WTH * 2) + q * 16,
             (const char*)(g_WT + (size_t)s * DN) + q * 16);
    }
    CP_COMMIT();

    // ======== Phase 3: 1-sync pipelined: stage(ch+1) | gemm(ch-1) | wc(ch) =
    float acc[3][4][4];
    #pragma unroll
    for (int mt = 0; mt < 3; mt++)
        #pragma unroll
        for (int j = 0; j < 4; j++)
            #pragma unroll
            for (int q = 0; q < 4; q++) acc[mt][j][q] = 0.f;

    int wt_next = 1;   // (ch+1)%3 at ch=0
    int wt_gemm = 2;   // (ch-1)%3 at ch=0 (unused until ch=1 where it's 0)

    for (int ch = 0; ch < NCH3; ch++) {
        // rotate mod-3 indices: wt_stage for ch+1, wt_gemm for ch-1
        wt_gemm = wt_next - 1;                 // (ch)%3 - 1 ... maintain directly:
        // recompute cleanly (cheap):
        const int m3   = ch % 3;               // WT buffer of chunk ch
        const int m3n  = (ch + 1) % 3;         // staging target
        const int m3p  = (ch + 2) % 3;         // == (ch-1)%3
        (void)wt_next; (void)wt_gemm;

        const int cur  = ch & 1;
        const int imgC = cur ? OFF_IMG1 : OFF_IMG0;
        const int capC = cur ? OFF_CAP1 : OFF_CAP0;
        const int aC   = cur ? OFF_A1   : OFF_A0;

        CP_WAIT0();          // stage(ch) landed (this thread's copies)
        __syncthreads();     // stage(ch) visible; sim(ch-1) visible; gemm(ch-2) done

        if (ch + 1 < NCH3) {
            const int imgN = cur ? OFF_IMG0 : OFF_IMG1;
            const int capN = cur ? OFF_CAP0 : OFF_CAP1;
            const int wtN  = (m3n == 0) ? OFF_WT0 : (m3n == 1) ? OFF_WT1 : OFF_WT2;
            const int dof = (ch + 1) * DC3;
            for (int idx = tid; idx < RN * (DC3 / 4); idx += NT) {
                int r = idx >> 3, d4 = idx & 7;
                CP16(sb + (imgN + r * ST3 + d4 * 4) * 4,
                     imgB + r * DN + dof + d4 * 4);
            }
            for (int idx = tid; idx < LN * (DC3 / 4); idx += NT) {
                int l = idx >> 3, d4 = idx & 7;
                CP16(sb + (capN + l * ST3 + d4 * 4) * 4,
                     capB + l * DN + dof + d4 * 4);
            }
            for (int idx = tid; idx < SN * 4; idx += NT) {
                int s = idx >> 2, q = idx & 3;
                CP16(sb + wtN * 4 + s * (WTH * 2) + q * 16,
                     (const char*)(g_WT + (size_t)s * DN + dof) + q * 16);
            }
            CP_COMMIT();
        }

        // GEMM(ch-1): A[(ch-1)&1], WT[(ch-1)%3]  (overlaps wc below on other pipe)
        if (ch > 0) {
            const int aP  = (cur ^ 1) ? OFF_A1 : OFF_A0;
            const int wtP = (m3p == 0) ? OFF_WT0 : (m3p == 1) ? OFF_WT1 : OFF_WT2;
            gemm_step((const __half*)(sm + aP), (const __half*)(sm + wtP),
                      acc, w, gq, tg);
        }

        // wc(ch): warp w owns l = 5w..5w+4, lane owns d = lane -> A[ch&1]
        {
            float wcv[5] = {0.f, 0.f, 0.f, 0.f, 0.f};
            #pragma unroll 3
            for (int r = 0; r < RN; r += 4) {
                float im0 = sm[imgC + (r + 0) * ST3 + lane];
                float im1 = sm[imgC + (r + 1) * ST3 + lane];
                float im2 = sm[imgC + (r + 2) * ST3 + lane];
                float im3 = sm[imgC + (r + 3) * ST3 + lane];
                #pragma unroll
                for (int ii = 0; ii < 5; ii++) {
                    float4 a4 = *(const float4*)(sAT + (5 * w + ii) * 40 + r);
                    wcv[ii] = fmaf(a4.x, im0, wcv[ii]);
                    wcv[ii] = fmaf(a4.y, im1, wcv[ii]);
                    wcv[ii] = fmaf(a4.z, im2, wcv[ii]);
                    wcv[ii] = fmaf(a4.w, im3, wcv[ii]);
                }
            }
            __half* sAh = (__half*)(sm + aC);
            #pragma unroll
            for (int ii = 0; ii < 5; ii++) {
                const int l = 5 * w + ii;
                float v = fmaf(wcv[ii], invl[ii], -sm[capC + l * ST3 + lane]);
                sAh[l * ATH + lane] = __float2half(v * v);
            }
        }
    }

    // final GEMM(NCH3-1)
    __syncthreads();
    {
        const int aP  = ((NCH3 - 1) & 1) ? OFF_A1 : OFF_A0;
        const int m3p = (NCH3 - 1) % 3;
        const int wtP = (m3p == 0) ? OFF_WT0 : (m3p == 1) ? OFF_WT1 : OFF_WT2;
        gemm_step((const __half*)(sm + aP), (const __half*)(sm + wtP),
                  acc, w, gq, tg);
    }

    // ======== Epilogue: +b, relu, per-row ssq (quad shfl), norm, store ====
    __syncthreads();
    float* sRed = sm + OFF_RED;
    #pragma unroll
    for (int mt = 0; mt < 3; mt++) {
        #pragma unroll
        for (int half = 0; half < 2; half++) {
            const int l = mt * 16 + gq + 8 * half;
            float ssq = 0.f;
            #pragma unroll
            for (int j = 0; j < 4; j++) {
                const int s = 32 * w + 8 * j + 2 * tg;
                float x0 = fmaxf(acc[mt][j][2 * half]     + sm[OFF_B + s],     0.f);
                float x1 = fmaxf(acc[mt][j][2 * half + 1] + sm[OFF_B + s + 1], 0.f);
                acc[mt][j][2 * half]     = x0;
                acc[mt][j][2 * half + 1] = x1;
                ssq = fmaf(x0, x0, ssq);
                ssq = fmaf(x1, x1, ssq);
            }
            ssq += __shfl_xor_sync(0xffffffffu, ssq, 1);
            ssq += __shfl_xor_sync(0xffffffffu, ssq, 2);
            if (tg == 0) sRed[l * 8 + w] = ssq;
        }
    }
    __syncthreads();
    const int clen = lens_g[c];
    if (tid < LN) {
        float ss = 0.f;
        #pragma unroll
        for (int q = 0; q < 8; q++) ss += sRed[tid * 8 + q];
        float inv = 1.f / (sqrtf(ss) + 1e-8f);
        sInv[tid] = (tid < clen) ? inv : 0.f;
    }
    __syncthreads();

    float* outB = out_g + (size_t)(c * IN_N + i) * (LN * SN);
    #pragma unroll
    for (int mt = 0; mt < 3; mt++) {
        #pragma unroll
        for (int half = 0; half < 2; half++) {
            const int l = mt * 16 + gq + 8 * half;
            if (l < LN) {
                float inv = sInv[l];
                #pragma unroll
                for (int j = 0; j < 4; j++) {
                    const int s = 32 * w + 8 * j + 2 * tg;
                    float2 o;
                    o.x = acc[mt][j][2 * half]     * inv;
                    o.y = acc[mt][j][2 * half + 1] * inv;
                    *(float2*)(outB + (size_t)l * SN + s) = o;
                }
            }
        }
    }
}

extern "C" void kernel_launch(void* const* d_in, const int* in_sizes, int n_in,
                              void* d_out, int out_size)
{
    const float* img  = (const float*)d_in[0];
    const float* cap  = (const float*)d_in[1];
    const int*   lens = (const int*)  d_in[2];
    const float* W    = (const float*)d_in[5];
    const float* b    = (const float*)d_in[6];
    float* out = (float*)d_out;
    (void)in_sizes; (void)n_in; (void)out_size;

    cudaFuncSetAttribute(graphembt_kernel,
                         cudaFuncAttributeMaxDynamicSharedMemorySize,
                         SMEM_FLOATS * sizeof(float));

    dim3 ggrid(IN_N, (RN * RN) / 8);
    gram_kernel<<<ggrid, 256>>>(img);
    wtrans_kernel<<<(DN * SN + 255) / 256, 256>>>(W);
    dim3 grid(IN_N, CN);
    graphembt_kernel<<<grid, NT, SMEM_FLOATS * sizeof(float)>>>(
        img, cap, lens, b, out);
}